// round 6
// baseline (speedup 1.0000x reference)
#include <cuda_runtime.h>
#include <cstdint>
#include <cstddef>

#define BB 2
#define HH 16
#define SEQ 2048
#define HD 128
#define TS 128
#define NCH (SEQ / TS)
#define SCALE 0.08838834764831845f

#define STR 132   // stride (floats) for Q/K/P tiles (conflict-free frag loads)
#define VSTR 136  // stride (floats) for V tile (conflict-free B-frag loads)

// k1 smem float offsets
#define O_K0 16896
#define O_K1 33792
#define O_MM 50688
#define O_LL 50816
#define O_PM 50944            // [4][128] per-colgroup max partials
#define O_PSM 51456           // [4][128] per-colgroup sum partials
#define O_MN 51968            // [128] merged new max
#define SMEM1 (52096 * 4)     // 208384 B
// k2 smem float offsets
#define O_V0 16896            // two V buffers of 128*136
#define O_M2 51712
#define O_L2 51840
#define SMEM2 (51968 * 4)     // 207872 B

// scratch: softmax stats + tf32-pre-rounded K/V copies
__device__ float g_rowM[BB * HH * SEQ];
__device__ float g_rowL[BB * HH * SEQ];
__device__ float g_kT[(size_t)BB * HH * SEQ * HD];
__device__ float g_vT[(size_t)BB * HH * SEQ * HD];

__device__ __forceinline__ uint32_t smem_u32(const void* p) {
    uint32_t a;
    asm("{ .reg .u64 t; cvta.to.shared.u64 t, %1; cvt.u32.u64 %0, t; }"
        : "=r"(a) : "l"(p));
    return a;
}
__device__ __forceinline__ float tf32r(float x) {  // round-to-nearest tf32
    uint32_t u; asm("cvt.rna.tf32.f32 %0, %1;" : "=r"(u) : "f"(x));
    return __uint_as_float(u);
}
__device__ __forceinline__ float4 t4(float4 v) {
    return make_float4(tf32r(v.x), tf32r(v.y), tf32r(v.z), tf32r(v.w));
}
// fast exp on fma/alu pipes, |rel err| ~1e-6 for x <= 0
__device__ __forceinline__ float fexp(float x) {
    x = fmaxf(x, -87.0f);
    float y = x * 1.442695041f;
    float t = y + 12582912.0f;
    int   n = __float_as_int(t) - 0x4B400000;
    float f = y - (t - 12582912.0f);
    float p = 1.33335581e-3f;
    p = fmaf(p, f, 9.61812910e-3f);
    p = fmaf(p, f, 5.55041087e-2f);
    p = fmaf(p, f, 2.40226507e-1f);
    p = fmaf(p, f, 6.93147182e-1f);
    p = fmaf(p, f, 1.0f);
    return p * __int_as_float((n + 127) << 23);
}
__device__ __forceinline__ void mma8(float* c, const uint32_t* a, uint32_t b0, uint32_t b1) {
    asm volatile(
        "mma.sync.aligned.m16n8k8.row.col.f32.tf32.tf32.f32 "
        "{%0,%1,%2,%3}, {%4,%5,%6,%7}, {%8,%9}, {%0,%1,%2,%3};"
        : "+f"(c[0]), "+f"(c[1]), "+f"(c[2]), "+f"(c[3])
        : "r"(a[0]), "r"(a[1]), "r"(a[2]), "r"(a[3]), "r"(b0), "r"(b1));
}
#define CP16(dst, src) \
    asm volatile("cp.async.cg.shared.global [%0], [%1], 16;" :: "r"(dst), "l"(src))
#define CP_COMMIT asm volatile("cp.async.commit_group;" ::: "memory")
#define CP_WAIT1 asm volatile("cp.async.wait_group 1;" ::: "memory")
#define CP_WAIT0 asm volatile("cp.async.wait_group 0;" ::: "memory")

// k0: pre-round a float array to tf32 (RNA) — feeds cp.async raw-byte staging
__global__ __launch_bounds__(512) void k_round(const float4* __restrict__ src,
                                               float4* __restrict__ dst) {
    int i = blockIdx.x * 512 + threadIdx.x;
    dst[i] = t4(src[i]);
}

// ---------------------------------------------------------------------------
// k1: raw scores via tf32 mma.sync -> attn buffer (scratch); online (m,l).
// grid (16, 32), 512 thr (16 warps: 4M x 4N, warp tile 32x32).
// K double-buffered cp.async; bias prefetched to regs; mask loaded in epilogue.
// ---------------------------------------------------------------------------
__global__ __launch_bounds__(512, 1) void k_scores(
    const float* __restrict__ q, const int* __restrict__ mask,
    const float* __restrict__ bias, float* __restrict__ attn) {
    extern __shared__ float S[];
    uint32_t* SU = (uint32_t*)S;
    const uint32_t smb = smem_u32(S);
    const int tid = threadIdx.x, w = tid >> 5, lane = tid & 31;
    const int qt = blockIdx.x, bh = blockIdx.y, b = bh >> 4, h = bh & 15;
    const int mg = w >> 2, ng = w & 3;
    const int lg = lane >> 2, lm = lane & 3;

    const float* qb = q + ((size_t)bh * SEQ + (size_t)qt * TS) * HD;
    const float* kb = g_kT + (size_t)bh * SEQ * HD;
    float* ab = attn + ((size_t)bh * SEQ + (size_t)qt * TS) * SEQ;
    const float* bb = bias + ((size_t)h * SEQ + (size_t)qt * TS) * SEQ;
    const int* mb = mask + ((size_t)b * SEQ + (size_t)qt * TS) * SEQ;

    // stage Q (tf32, resident) + stats init + cp.async K(0)
    #pragma unroll
    for (int p = 0; p < 8; p++) {
        int idx = p * 2048 + tid * 4;
        int r = idx >> 7, c = idx & 127;
        *(float4*)(S + r * STR + c) = t4(*(const float4*)(qb + idx));
    }
    if (tid < 128) { S[O_MM + tid] = -3.0e38f; S[O_LL + tid] = 0.0f; }
    #pragma unroll
    for (int p = 0; p < 8; p++) {
        int idx = p * 2048 + tid * 4;
        int r = idx >> 7, c = idx & 127;
        CP16(smb + (uint32_t)(O_K0 + r * STR + c) * 4u, kb + idx);
    }
    CP_COMMIT;

    for (int i = 0; i < NCH; i++) {
        if (i < NCH - 1) {  // prefetch K(i+1) into other buffer
            const float* kc2 = kb + (size_t)(i + 1) * TS * HD;
            const int kbn = O_K0 + (((i + 1) & 1) ? (O_K1 - O_K0) : 0);
            #pragma unroll
            for (int p = 0; p < 8; p++) {
                int idx = p * 2048 + tid * 4;
                int r = idx >> 7, c = idx & 127;
                CP16(smb + (uint32_t)(kbn + r * STR + c) * 4u, kc2 + idx);
            }
            CP_COMMIT;
        }
        // bias prefetch into regs (consumed after MMA -> latency hidden)
        float2 breg[2][2][4];
        #pragma unroll
        for (int mt = 0; mt < 2; mt++)
            #pragma unroll
            for (int hh = 0; hh < 2; hh++) {
                int r = mg * 32 + mt * 16 + hh * 8 + lg;
                #pragma unroll
                for (int nt = 0; nt < 4; nt++)
                    breg[mt][hh][nt] = *(const float2*)(
                        bb + (size_t)r * SEQ + (size_t)i * TS + ng * 32 + nt * 8 + 2 * lm);
            }
        if (i < NCH - 1) { CP_WAIT1; } else { CP_WAIT0; }
        __syncthreads();

        const int kbase = O_K0 + (i & 1) * (O_K1 - O_K0);
        float acc[2][4][4];
        #pragma unroll
        for (int mt = 0; mt < 2; mt++)
            #pragma unroll
            for (int nt = 0; nt < 4; nt++)
                #pragma unroll
                for (int j = 0; j < 4; j++) acc[mt][nt][j] = 0.0f;

        #pragma unroll 4
        for (int ks = 0; ks < 16; ks++) {
            const int kc = ks * 8;
            uint32_t a[2][4];
            #pragma unroll
            for (int mt = 0; mt < 2; mt++) {
                int r0 = mg * 32 + mt * 16 + lg;
                a[mt][0] = SU[r0 * STR + kc + lm];
                a[mt][1] = SU[(r0 + 8) * STR + kc + lm];
                a[mt][2] = SU[r0 * STR + kc + lm + 4];
                a[mt][3] = SU[(r0 + 8) * STR + kc + lm + 4];
            }
            #pragma unroll
            for (int nt = 0; nt < 4; nt++) {
                int nr = ng * 32 + nt * 8 + lg;
                uint32_t b0 = SU[kbase + nr * STR + kc + lm];
                uint32_t b1 = SU[kbase + nr * STR + kc + lm + 4];
                mma8(acc[0][nt], a[0], b0, b1);
                mma8(acc[1][nt], a[1], b0, b1);
            }
        }

        // ep-a: scale+bias+mask, write raw scores, per-colgroup row max
        #pragma unroll
        for (int mt = 0; mt < 2; mt++)
            #pragma unroll
            for (int hh = 0; hh < 2; hh++) {
                int r = mg * 32 + mt * 16 + hh * 8 + lg;
                const size_t rb = (size_t)r * SEQ + (size_t)i * TS;
                float rm = -3.0e38f;
                #pragma unroll
                for (int nt = 0; nt < 4; nt++) {
                    int col = ng * 32 + nt * 8 + 2 * lm;
                    int2 mv = *(const int2*)(mb + rb + col);
                    float2 bv = breg[mt][hh][nt];
                    float s0 = fmaf(acc[mt][nt][2 * hh], SCALE, bv.x);
                    float s1 = fmaf(acc[mt][nt][2 * hh + 1], SCALE, bv.y);
                    if (mv.x == 0) s0 = -1.0e9f;
                    if (mv.y == 0) s1 = -1.0e9f;
                    *(float2*)(ab + rb + col) = make_float2(s0, s1);
                    acc[mt][nt][2 * hh] = s0;
                    acc[mt][nt][2 * hh + 1] = s1;
                    rm = fmaxf(rm, fmaxf(s0, s1));
                }
                rm = fmaxf(rm, __shfl_xor_sync(0xffffffffu, rm, 1));
                rm = fmaxf(rm, __shfl_xor_sync(0xffffffffu, rm, 2));
                if (lm == 0) S[O_PM + ng * 128 + r] = rm;
            }
        __syncthreads();

        // ep-b: merged max, per-colgroup sum of exp
        #pragma unroll
        for (int mt = 0; mt < 2; mt++)
            #pragma unroll
            for (int hh = 0; hh < 2; hh++) {
                int r = mg * 32 + mt * 16 + hh * 8 + lg;
                float mn = fmaxf(fmaxf(S[O_MM + r], S[O_PM + r]),
                                 fmaxf(fmaxf(S[O_PM + 128 + r], S[O_PM + 256 + r]),
                                       S[O_PM + 384 + r]));
                float e = 0.0f;
                #pragma unroll
                for (int nt = 0; nt < 4; nt++)
                    e += fexp(acc[mt][nt][2 * hh] - mn) +
                         fexp(acc[mt][nt][2 * hh + 1] - mn);
                e += __shfl_xor_sync(0xffffffffu, e, 1);
                e += __shfl_xor_sync(0xffffffffu, e, 2);
                if (lm == 0) {
                    S[O_PSM + ng * 128 + r] = e;
                    if (ng == 0) S[O_MN + r] = mn;
                }
            }
        __syncthreads();
        if (tid < 128) {
            float mn = S[O_MN + tid];
            S[O_LL + tid] = S[O_LL + tid] * fexp(S[O_MM + tid] - mn) +
                            S[O_PSM + tid] + S[O_PSM + 128 + tid] +
                            S[O_PSM + 256 + tid] + S[O_PSM + 384 + tid];
            S[O_MM + tid] = mn;
        }
        __syncthreads();
    }
    if (tid < 128) {
        g_rowM[(size_t)bh * SEQ + qt * TS + tid] = S[O_MM + tid];
        g_rowL[(size_t)bh * SEQ + qt * TS + tid] = S[O_LL + tid];
    }
}

// ---------------------------------------------------------------------------
// k2: p = exp(s-m)/l -> final attn (in place); out = P @ V via tf32 mma.sync.
// V double-buffered cp.async (pre-rounded); raw P prefetched to regs.
// ---------------------------------------------------------------------------
__global__ __launch_bounds__(512, 1) void k_out(
    float* __restrict__ attn, float* __restrict__ out) {
    extern __shared__ float S[];
    uint32_t* SU = (uint32_t*)S;
    const uint32_t smb = smem_u32(S);
    const int tid = threadIdx.x, w = tid >> 5, lane = tid & 31;
    const int qt = blockIdx.x, bh = blockIdx.y;
    const int mg = w >> 2, ng = w & 3;
    const int lg = lane >> 2, lm = lane & 3;

    const float* vb = g_vT + (size_t)bh * SEQ * HD;
    float* ab = attn + ((size_t)bh * SEQ + (size_t)qt * TS) * SEQ;
    float* ob = out + ((size_t)bh * SEQ + (size_t)qt * TS) * HD;

    if (tid < 128) {
        S[O_M2 + tid] = g_rowM[(size_t)bh * SEQ + qt * TS + tid];
        S[O_L2 + tid] = 1.0f / g_rowL[(size_t)bh * SEQ + qt * TS + tid];
    }
    // cp.async V(0) + praw(0) register prefetch
    #pragma unroll
    for (int p = 0; p < 8; p++) {
        int idx = p * 2048 + tid * 4;
        int r = idx >> 7, c = idx & 127;
        CP16(smb + (uint32_t)(O_V0 + r * VSTR + c) * 4u, vb + idx);
    }
    CP_COMMIT;
    float4 pr[8];
    #pragma unroll
    for (int p = 0; p < 8; p++) {
        int idx = p * 2048 + tid * 4;
        pr[p] = *(const float4*)(ab + (size_t)(idx >> 7) * SEQ + (idx & 127));
    }
    float acc[2][4][4];
    #pragma unroll
    for (int mt = 0; mt < 2; mt++)
        #pragma unroll
        for (int nt = 0; nt < 4; nt++)
            #pragma unroll
            for (int j = 0; j < 4; j++) acc[mt][nt][j] = 0.0f;
    __syncthreads();

    for (int i = 0; i < NCH; i++) {
        if (i < NCH - 1) {  // prefetch V(i+1)
            const float* vc = vb + (size_t)(i + 1) * TS * HD;
            const int vbn = O_V0 + ((i + 1) & 1) * (128 * VSTR);
            #pragma unroll
            for (int p = 0; p < 8; p++) {
                int idx = p * 2048 + tid * 4;
                int r = idx >> 7, c = idx & 127;
                CP16(smb + (uint32_t)(vbn + r * VSTR + c) * 4u, vc + idx);
            }
            CP_COMMIT;
        }
        // stage P(i): exp-normalize from regs, write final attn + tf32 smem
        #pragma unroll
        for (int p = 0; p < 8; p++) {
            int idx = p * 2048 + tid * 4;
            int r = idx >> 7, c = idx & 127;
            float m = S[O_M2 + r], il = S[O_L2 + r];
            float4 s4 = pr[p];
            float4 p4 = make_float4(fexp(s4.x - m) * il, fexp(s4.y - m) * il,
                                    fexp(s4.z - m) * il, fexp(s4.w - m) * il);
            *(float4*)(ab + (size_t)r * SEQ + (size_t)i * TS + c) = p4;
            *(float4*)(S + r * STR + c) = t4(p4);
        }
        if (i < NCH - 1) { CP_WAIT1; } else { CP_WAIT0; }
        __syncthreads();
        if (i < NCH - 1) {  // praw(i+1) regs: latency hides under MMA
            #pragma unroll
            for (int p = 0; p < 8; p++) {
                int idx = p * 2048 + tid * 4;
                pr[p] = *(const float4*)(
                    ab + (size_t)(idx >> 7) * SEQ + (size_t)(i + 1) * TS + (idx & 127));
            }
        }
        const int vbase = O_V0 + (i & 1) * (128 * VSTR);
        #pragma unroll 4
        for (int ks = 0; ks < 16; ks++) {
            const int kc = ks * 8;
            uint32_t a[2][4];
            #pragma unroll
            for (int mt = 0; mt < 2; mt++) {
                int r0 = mg * 32 + mt * 16 + lg;
                a[mt][0] = SU[r0 * STR + kc + lm];
                a[mt][1] = SU[(r0 + 8) * STR + kc + lm];
                a[mt][2] = SU[r0 * STR + kc + lm + 4];
                a[mt][3] = SU[(r0 + 8) * STR + kc + lm + 4];
            }
            #pragma unroll
            for (int nt = 0; nt < 4; nt++) {
                int nc = ng * 32 + nt * 8 + lg;
                uint32_t b0 = SU[vbase + (kc + lm) * VSTR + nc];
                uint32_t b1 = SU[vbase + (kc + lm + 4) * VSTR + nc];
                mma8(acc[0][nt], a[0], b0, b1);
                mma8(acc[1][nt], a[1], b0, b1);
            }
        }
        __syncthreads();
    }

    // out epilogue
    #pragma unroll
    for (int mt = 0; mt < 2; mt++)
        #pragma unroll
        for (int hh = 0; hh < 2; hh++) {
            int r = mg * 32 + mt * 16 + hh * 8 + lg;
            #pragma unroll
            for (int nt = 0; nt < 4; nt++) {
                int col = ng * 32 + nt * 8 + 2 * lm;
                *(float2*)(ob + (size_t)r * HD + col) =
                    make_float2(acc[mt][nt][2 * hh], acc[mt][nt][2 * hh + 1]);
            }
        }
}

extern "C" void kernel_launch(void* const* d_in, const int* in_sizes, int n_in,
                              void* d_out, int out_size) {
    const float* q    = (const float*)d_in[0];
    const float* k    = (const float*)d_in[1];
    const float* v    = (const float*)d_in[2];
    const int*   mask = (const int*)d_in[3];
    const float* bias = (const float*)d_in[4];

    float* out  = (float*)d_out;
    float* attn = out + (size_t)BB * HH * SEQ * HD;

    float* kT; cudaGetSymbolAddress((void**)&kT, g_kT);
    float* vT; cudaGetSymbolAddress((void**)&vT, g_vT);

    cudaFuncSetAttribute(k_scores, cudaFuncAttributeMaxDynamicSharedMemorySize, SMEM1);
    cudaFuncSetAttribute(k_out,    cudaFuncAttributeMaxDynamicSharedMemorySize, SMEM2);

    const int n4 = (BB * HH * SEQ * HD) / 4;  // 2097152
    k_round<<<n4 / 512, 512>>>((const float4*)k, (float4*)kT);
    k_round<<<n4 / 512, 512>>>((const float4*)v, (float4*)vT);

    dim3 grid(NCH, BB * HH);
    k_scores<<<grid, 512, SMEM1>>>(q, mask, bias, attn);
    k_out<<<grid, 512, SMEM2>>>(attn, out);
}

// round 8
// speedup vs baseline: 1.3730x; 1.3730x over previous
#include <cuda_runtime.h>
#include <cstdint>
#include <cstddef>

#define BB 2
#define HH 16
#define SEQ 2048
#define HD 128
#define TQ 64            // q rows per block
#define TK 128           // k cols per chunk
#define NCH (SEQ / TK)
#define SCALE 0.08838834764831845f

#define STR 132   // stride (floats) Q/K/P tiles (conflict-free frag loads)
#define VSTR 136  // stride (floats) V tile (conflict-free B-frag loads)

// k1 smem float offsets
#define O_Q   0                    // [64][132]
#define O_K   8448                 // [128][132]
#define O_MM  25344                // [64] running max
#define O_LL  25408                // [64] running sumexp
#define O_PM  25472                // [4][64] partial max
#define O_PSM 25728                // [4][64] partial sum
#define O_MN  25984                // [64] merged max
#define SMEM1 (26048 * 4)          // 104192 B
// k2 smem float offsets
#define O_P   0                    // [64][132]
#define O_V   8448                 // [128][136]
#define O_M2  25856                // [64]
#define O_L2  25920                // [64]
#define SMEM2 (25984 * 4)          // 103936 B

// scratch: softmax stats + tf32-pre-rounded K/V
__device__ float g_rowM[BB * HH * SEQ];
__device__ float g_rowL[BB * HH * SEQ];
__device__ float g_kT[(size_t)BB * HH * SEQ * HD];
__device__ float g_vT[(size_t)BB * HH * SEQ * HD];

__device__ __forceinline__ uint32_t smem_u32(const void* p) {
    uint32_t a;
    asm("{ .reg .u64 t; cvta.to.shared.u64 t, %1; cvt.u32.u64 %0, t; }"
        : "=r"(a) : "l"(p));
    return a;
}
__device__ __forceinline__ float tf32r(float x) {  // round-to-nearest tf32
    uint32_t u; asm("cvt.rna.tf32.f32 %0, %1;" : "=r"(u) : "f"(x));
    return __uint_as_float(u);
}
__device__ __forceinline__ float4 t4(float4 v) {
    return make_float4(tf32r(v.x), tf32r(v.y), tf32r(v.z), tf32r(v.w));
}
// fast exp on fma/alu pipes, |rel err| ~1e-6 for x <= 0
__device__ __forceinline__ float fexp(float x) {
    x = fmaxf(x, -87.0f);
    float y = x * 1.442695041f;
    float t = y + 12582912.0f;
    int   n = __float_as_int(t) - 0x4B400000;
    float f = y - (t - 12582912.0f);
    float p = 1.33335581e-3f;
    p = fmaf(p, f, 9.61812910e-3f);
    p = fmaf(p, f, 5.55041087e-2f);
    p = fmaf(p, f, 2.40226507e-1f);
    p = fmaf(p, f, 6.93147182e-1f);
    p = fmaf(p, f, 1.0f);
    return p * __int_as_float((n + 127) << 23);
}
__device__ __forceinline__ void mma8(float* c, const uint32_t* a, uint32_t b0, uint32_t b1) {
    asm volatile(
        "mma.sync.aligned.m16n8k8.row.col.f32.tf32.tf32.f32 "
        "{%0,%1,%2,%3}, {%4,%5,%6,%7}, {%8,%9}, {%0,%1,%2,%3};"
        : "+f"(c[0]), "+f"(c[1]), "+f"(c[2]), "+f"(c[3])
        : "r"(a[0]), "r"(a[1]), "r"(a[2]), "r"(a[3]), "r"(b0), "r"(b1));
}
#define CP16(dst, src) \
    asm volatile("cp.async.cg.shared.global [%0], [%1], 16;" :: "r"(dst), "l"(src))
#define CP_COMMIT asm volatile("cp.async.commit_group;" ::: "memory")
#define CP_WAIT0 asm volatile("cp.async.wait_group 0;" ::: "memory")

// k0: pre-round float array to tf32 (RNA) — feeds cp.async raw-byte staging
__global__ __launch_bounds__(512) void k_round(const float4* __restrict__ src,
                                               float4* __restrict__ dst) {
    int i = blockIdx.x * 512 + threadIdx.x;
    dst[i] = t4(src[i]);
}

// ---------------------------------------------------------------------------
// k1: raw scores (scale folded into Q, + bias, mask) -> attn buffer; (m,l).
// grid (32, 32), 256 thr (8 warps: 2M x 4N, warp tile 32x32), 2 CTAs/SM.
// ---------------------------------------------------------------------------
__global__ __launch_bounds__(256, 2) void k_scores(
    const float* __restrict__ q, const int* __restrict__ mask,
    const float* __restrict__ bias, float* __restrict__ attn) {
    extern __shared__ float S[];
    uint32_t* SU = (uint32_t*)S;
    const uint32_t smb = smem_u32(S);
    const int tid = threadIdx.x, w = tid >> 5, lane = tid & 31;
    const int qt = blockIdx.x, bh = blockIdx.y, b = bh >> 4, h = bh & 15;
    const int mg = w >> 2, ng = w & 3;
    const int lg = lane >> 2, lm = lane & 3;

    const float* qb = q + ((size_t)bh * SEQ + (size_t)qt * TQ) * HD;
    const float* kb = g_kT + (size_t)bh * SEQ * HD;
    float* ab = attn + ((size_t)bh * SEQ + (size_t)qt * TQ) * SEQ;
    const float* bb = bias + ((size_t)h * SEQ + (size_t)qt * TQ) * SEQ;
    const int* mb = mask + ((size_t)b * SEQ + (size_t)qt * TQ) * SEQ;

    // stage Q (pre-scaled, tf32) + stats init + cp.async K(0)
    #pragma unroll
    for (int p = 0; p < 8; p++) {
        int idx = p * 1024 + tid * 4;
        int r = idx >> 7, c = idx & 127;
        float4 qv = *(const float4*)(qb + idx);
        qv.x *= SCALE; qv.y *= SCALE; qv.z *= SCALE; qv.w *= SCALE;
        *(float4*)(S + O_Q + r * STR + c) = t4(qv);
    }
    if (tid < 64) { S[O_MM + tid] = -3.0e38f; S[O_LL + tid] = 0.0f; }
    #pragma unroll
    for (int p = 0; p < 16; p++) {
        int idx = p * 1024 + tid * 4;
        int r = idx >> 7, c = idx & 127;
        CP16(smb + (uint32_t)(O_K + r * STR + c) * 4u, kb + idx);
    }
    CP_COMMIT;
    CP_WAIT0;
    __syncthreads();

    for (int i = 0; i < NCH; i++) {
        float acc[2][4][4];
        #pragma unroll
        for (int mt = 0; mt < 2; mt++)
            #pragma unroll
            for (int nt = 0; nt < 4; nt++)
                #pragma unroll
                for (int j = 0; j < 4; j++) acc[mt][nt][j] = 0.0f;

        #pragma unroll 4
        for (int ks = 0; ks < 16; ks++) {
            const int kc = ks * 8;
            uint32_t a[2][4];
            #pragma unroll
            for (int mt = 0; mt < 2; mt++) {
                int r0 = mg * 32 + mt * 16 + lg;
                a[mt][0] = SU[O_Q + r0 * STR + kc + lm];
                a[mt][1] = SU[O_Q + (r0 + 8) * STR + kc + lm];
                a[mt][2] = SU[O_Q + r0 * STR + kc + lm + 4];
                a[mt][3] = SU[O_Q + (r0 + 8) * STR + kc + lm + 4];
            }
            #pragma unroll
            for (int nt = 0; nt < 4; nt++) {
                int nr = ng * 32 + nt * 8 + lg;
                uint32_t b0 = SU[O_K + nr * STR + kc + lm];
                uint32_t b1 = SU[O_K + nr * STR + kc + lm + 4];
                mma8(acc[0][nt], a[0], b0, b1);
                mma8(acc[1][nt], a[1], b0, b1);
            }
        }

        // ep-a: + bias, mask, write raw scores, per-colgroup row max
        #pragma unroll
        for (int mt = 0; mt < 2; mt++)
            #pragma unroll
            for (int hh = 0; hh < 2; hh++) {
                int r = mg * 32 + mt * 16 + hh * 8 + lg;
                const size_t rb = (size_t)r * SEQ + (size_t)i * TK;
                float rm = -3.0e38f;
                #pragma unroll
                for (int nt = 0; nt < 4; nt++) {
                    int col = ng * 32 + nt * 8 + 2 * lm;
                    float2 bv = *(const float2*)(bb + rb + col);
                    int2 mv = *(const int2*)(mb + rb + col);
                    float s0 = acc[mt][nt][2 * hh] + bv.x;
                    float s1 = acc[mt][nt][2 * hh + 1] + bv.y;
                    if (mv.x == 0) s0 = -1.0e9f;
                    if (mv.y == 0) s1 = -1.0e9f;
                    *(float2*)(ab + rb + col) = make_float2(s0, s1);
                    acc[mt][nt][2 * hh] = s0;
                    acc[mt][nt][2 * hh + 1] = s1;
                    rm = fmaxf(rm, fmaxf(s0, s1));
                }
                rm = fmaxf(rm, __shfl_xor_sync(0xffffffffu, rm, 1));
                rm = fmaxf(rm, __shfl_xor_sync(0xffffffffu, rm, 2));
                if (lm == 0) S[O_PM + ng * 64 + r] = rm;
            }
        __syncthreads();
        // K buffer free: start next chunk's load, overlaps ep-b
        if (i < NCH - 1) {
            const float* kc2 = kb + (size_t)(i + 1) * TK * HD;
            #pragma unroll
            for (int p = 0; p < 16; p++) {
                int idx = p * 1024 + tid * 4;
                int r = idx >> 7, c = idx & 127;
                CP16(smb + (uint32_t)(O_K + r * STR + c) * 4u, kc2 + idx);
            }
            CP_COMMIT;
        }
        // ep-b: merged max, per-colgroup sum of exp
        #pragma unroll
        for (int mt = 0; mt < 2; mt++)
            #pragma unroll
            for (int hh = 0; hh < 2; hh++) {
                int r = mg * 32 + mt * 16 + hh * 8 + lg;
                float mn = fmaxf(fmaxf(S[O_MM + r], S[O_PM + r]),
                                 fmaxf(fmaxf(S[O_PM + 64 + r], S[O_PM + 128 + r]),
                                       S[O_PM + 192 + r]));
                float e = 0.0f;
                #pragma unroll
                for (int nt = 0; nt < 4; nt++)
                    e += fexp(acc[mt][nt][2 * hh] - mn) +
                         fexp(acc[mt][nt][2 * hh + 1] - mn);
                e += __shfl_xor_sync(0xffffffffu, e, 1);
                e += __shfl_xor_sync(0xffffffffu, e, 2);
                if (lm == 0) {
                    S[O_PSM + ng * 64 + r] = e;
                    if (ng == 0) S[O_MN + r] = mn;
                }
            }
        __syncthreads();
        if (tid < 64) {
            float mn = S[O_MN + tid];
            S[O_LL + tid] = S[O_LL + tid] * fexp(S[O_MM + tid] - mn) +
                            S[O_PSM + tid] + S[O_PSM + 64 + tid] +
                            S[O_PSM + 128 + tid] + S[O_PSM + 192 + tid];
            S[O_MM + tid] = mn;
        }
        CP_WAIT0;
        __syncthreads();
    }
    if (tid < 64) {
        g_rowM[(size_t)bh * SEQ + qt * TQ + tid] = S[O_MM + tid];
        g_rowL[(size_t)bh * SEQ + qt * TQ + tid] = S[O_LL + tid];
    }
}

// ---------------------------------------------------------------------------
// k2: p = exp(s-m)/l -> final attn (in place); out = P @ V, 2 CTAs/SM.
// ---------------------------------------------------------------------------
__global__ __launch_bounds__(256, 2) void k_out(
    float* __restrict__ attn, float* __restrict__ out) {
    extern __shared__ float S[];
    uint32_t* SU = (uint32_t*)S;
    const uint32_t smb = smem_u32(S);
    const int tid = threadIdx.x, w = tid >> 5, lane = tid & 31;
    const int qt = blockIdx.x, bh = blockIdx.y;
    const int mg = w >> 2, ng = w & 3;
    const int lg = lane >> 2, lm = lane & 3;

    const float* vb = g_vT + (size_t)bh * SEQ * HD;
    float* ab = attn + ((size_t)bh * SEQ + (size_t)qt * TQ) * SEQ;
    float* ob = out + ((size_t)bh * SEQ + (size_t)qt * TQ) * HD;

    if (tid < 64) {
        S[O_M2 + tid] = g_rowM[(size_t)bh * SEQ + qt * TQ + tid];
        S[O_L2 + tid] = 1.0f / g_rowL[(size_t)bh * SEQ + qt * TQ + tid];
    }
    #pragma unroll
    for (int p = 0; p < 16; p++) {
        int idx = p * 1024 + tid * 4;
        int r = idx >> 7, c = idx & 127;
        CP16(smb + (uint32_t)(O_V + r * VSTR + c) * 4u, vb + idx);
    }
    CP_COMMIT;

    float acc[2][4][4];
    #pragma unroll
    for (int mt = 0; mt < 2; mt++)
        #pragma unroll
        for (int nt = 0; nt < 4; nt++)
            #pragma unroll
            for (int j = 0; j < 4; j++) acc[mt][nt][j] = 0.0f;
    __syncthreads();   // covers stats init

    for (int i = 0; i < NCH; i++) {
        // stage P(i): read raw (coalesced), normalize, write final attn, stash
        #pragma unroll
        for (int p = 0; p < 8; p++) {          // 8*1024 = 64 rows * 128 cols
            int idx = p * 1024 + tid * 4;
            int r = idx >> 7, c = idx & 127;
            float* ap = ab + (size_t)r * SEQ + (size_t)i * TK + c;
            float4 s4 = *(const float4*)ap;
            float m = S[O_M2 + r], il = S[O_L2 + r];
            float4 p4 = make_float4(fexp(s4.x - m) * il, fexp(s4.y - m) * il,
                                    fexp(s4.z - m) * il, fexp(s4.w - m) * il);
            *(float4*)ap = p4;
            *(float4*)(S + O_P + r * STR + c) = t4(p4);
        }
        CP_WAIT0;
        __syncthreads();   // V(i) + P(i) ready

        #pragma unroll 4
        for (int ks = 0; ks < 16; ks++) {
            const int kc = ks * 8;
            uint32_t a[2][4];
            #pragma unroll
            for (int mt = 0; mt < 2; mt++) {
                int r0 = mg * 32 + mt * 16 + lg;
                a[mt][0] = SU[O_P + r0 * STR + kc + lm];
                a[mt][1] = SU[O_P + (r0 + 8) * STR + kc + lm];
                a[mt][2] = SU[O_P + r0 * STR + kc + lm + 4];
                a[mt][3] = SU[O_P + (r0 + 8) * STR + kc + lm + 4];
            }
            #pragma unroll
            for (int nt = 0; nt < 4; nt++) {
                int nc = ng * 32 + nt * 8 + lg;
                uint32_t b0 = SU[O_V + (kc + lm) * VSTR + nc];
                uint32_t b1 = SU[O_V + (kc + lm + 4) * VSTR + nc];
                mma8(acc[0][nt], a[0], b0, b1);
                mma8(acc[1][nt], a[1], b0, b1);
            }
        }
        __syncthreads();   // all warps done with V(i)
        if (i < NCH - 1) { // V(i+1) load overlaps next P staging
            const float* vc = vb + (size_t)(i + 1) * TK * HD;
            #pragma unroll
            for (int p = 0; p < 16; p++) {
                int idx = p * 1024 + tid * 4;
                int r = idx >> 7, c = idx & 127;
                CP16(smb + (uint32_t)(O_V + r * VSTR + c) * 4u, vc + idx);
            }
            CP_COMMIT;
        }
    }

    // out epilogue
    #pragma unroll
    for (int mt = 0; mt < 2; mt++)
        #pragma unroll
        for (int hh = 0; hh < 2; hh++) {
            int r = mg * 32 + mt * 16 + hh * 8 + lg;
            #pragma unroll
            for (int nt = 0; nt < 4; nt++) {
                int col = ng * 32 + nt * 8 + 2 * lm;
                *(float2*)(ob + (size_t)r * HD + col) =
                    make_float2(acc[mt][nt][2 * hh], acc[mt][nt][2 * hh + 1]);
            }
        }
}

extern "C" void kernel_launch(void* const* d_in, const int* in_sizes, int n_in,
                              void* d_out, int out_size) {
    const float* q    = (const float*)d_in[0];
    const float* k    = (const float*)d_in[1];
    const float* v    = (const float*)d_in[2];
    const int*   mask = (const int*)d_in[3];
    const float* bias = (const float*)d_in[4];

    float* out  = (float*)d_out;
    float* attn = out + (size_t)BB * HH * SEQ * HD;

    float* kT; cudaGetSymbolAddress((void**)&kT, g_kT);
    float* vT; cudaGetSymbolAddress((void**)&vT, g_vT);

    cudaFuncSetAttribute(k_scores, cudaFuncAttributeMaxDynamicSharedMemorySize, SMEM1);
    cudaFuncSetAttribute(k_out,    cudaFuncAttributeMaxDynamicSharedMemorySize, SMEM2);

    const int n4 = (BB * HH * SEQ * HD) / 4;
    k_round<<<n4 / 512, 512>>>((const float4*)k, (float4*)kT);
    k_round<<<n4 / 512, 512>>>((const float4*)v, (float4*)vT);

    dim3 grid(SEQ / TQ, BB * HH);
    k_scores<<<grid, 256, SMEM1>>>(q, mask, bias, attn);
    k_out<<<grid, 256, SMEM2>>>(attn, out);
}

// round 9
// speedup vs baseline: 1.5679x; 1.1419x over previous
#include <cuda_runtime.h>
#include <cstdint>
#include <cstddef>

#define BB 2
#define HH 16
#define SEQ 2048
#define HD 128
#define TQ 64            // q rows per block
#define TKK 64           // k positions per chunk
#define NCH (SEQ / TKK)  // 32
#define SCALE 0.08838834764831845f

#define STR 132   // stride (floats) Q/K tiles
#define PSTR 68   // stride (floats) P tile (64 cols + 4)
#define VSTR 136  // stride (floats) V tile

// k1 smem float offsets
#define O_Q   0                    // [64][132]
#define O_K0  8448                 // [64][132]
#define O_K1  16896                // [64][132]
#define O_PMX 25344                // [2][64] warp-local max
#define O_PSM 25472                // [2][64] warp-local sumexp
#define O_MM  25600                // [64] running max
#define O_LL  25664                // [64] running sum
#define SMEM1 (25728 * 4)          // 102912 B
// k2 smem float offsets
#define O_P0  0                    // [64][68]
#define O_P1  4352
#define O_V0  8704                 // [64][136]
#define O_V1  17408
#define O_M2  26112                // [64]
#define O_L2  26176                // [64]
#define SMEM2 (26240 * 4)          // 104960 B

// scratch: softmax stats + tf32-pre-rounded K/V
__device__ float g_rowM[BB * HH * SEQ];
__device__ float g_rowL[BB * HH * SEQ];
__device__ float g_kT[(size_t)BB * HH * SEQ * HD];
__device__ float g_vT[(size_t)BB * HH * SEQ * HD];

__device__ __forceinline__ uint32_t smem_u32(const void* p) {
    uint32_t a;
    asm("{ .reg .u64 t; cvta.to.shared.u64 t, %1; cvt.u32.u64 %0, t; }"
        : "=r"(a) : "l"(p));
    return a;
}
__device__ __forceinline__ float tf32r(float x) {  // round-to-nearest tf32
    uint32_t u; asm("cvt.rna.tf32.f32 %0, %1;" : "=r"(u) : "f"(x));
    return __uint_as_float(u);
}
__device__ __forceinline__ float4 t4(float4 v) {
    return make_float4(tf32r(v.x), tf32r(v.y), tf32r(v.z), tf32r(v.w));
}
// fast exp on fma/alu pipes, |rel err| ~1e-6 for x <= 0
__device__ __forceinline__ float fexp(float x) {
    x = fmaxf(x, -87.0f);
    float y = x * 1.442695041f;
    float t = y + 12582912.0f;
    int   n = __float_as_int(t) - 0x4B400000;
    float f = y - (t - 12582912.0f);
    float p = 1.33335581e-3f;
    p = fmaf(p, f, 9.61812910e-3f);
    p = fmaf(p, f, 5.55041087e-2f);
    p = fmaf(p, f, 2.40226507e-1f);
    p = fmaf(p, f, 6.93147182e-1f);
    p = fmaf(p, f, 1.0f);
    return p * __int_as_float((n + 127) << 23);
}
__device__ __forceinline__ void mma8(float* c, const uint32_t* a, uint32_t b0, uint32_t b1) {
    asm volatile(
        "mma.sync.aligned.m16n8k8.row.col.f32.tf32.tf32.f32 "
        "{%0,%1,%2,%3}, {%4,%5,%6,%7}, {%8,%9}, {%0,%1,%2,%3};"
        : "+f"(c[0]), "+f"(c[1]), "+f"(c[2]), "+f"(c[3])
        : "r"(a[0]), "r"(a[1]), "r"(a[2]), "r"(a[3]), "r"(b0), "r"(b1));
}
#define CP16(dst, src) \
    asm volatile("cp.async.cg.shared.global [%0], [%1], 16;" :: "r"(dst), "l"(src))
#define CP_COMMIT asm volatile("cp.async.commit_group;" ::: "memory")
#define CP_WAIT0 asm volatile("cp.async.wait_group 0;" ::: "memory")
#define CP_WAIT1 asm volatile("cp.async.wait_group 1;" ::: "memory")

// k0: pre-round float array to tf32 (RNA) — feeds cp.async raw-byte staging
__global__ __launch_bounds__(512) void k_round(const float4* __restrict__ src,
                                               float4* __restrict__ dst) {
    int i = blockIdx.x * 512 + threadIdx.x;
    dst[i] = t4(src[i]);
}

// ---------------------------------------------------------------------------
// k1: raw scores (scale in Q, + bias, mask) -> attn buffer; online (m,l).
// grid (32, 32), 256 thr (8 warps: 4M x 2N, warp tile 16x32), 2 CTAs/SM.
// K double-buffered cp.async; bias/mask register-prefetched one chunk ahead;
// warp-local softmax partials -> 2 syncs per chunk.
// ---------------------------------------------------------------------------
__global__ __launch_bounds__(256, 2) void k_scores(
    const float* __restrict__ q, const int* __restrict__ mask,
    const float* __restrict__ bias, float* __restrict__ attn) {
    extern __shared__ float S[];
    uint32_t* SU = (uint32_t*)S;
    const uint32_t smb = smem_u32(S);
    const int tid = threadIdx.x, w = tid >> 5, lane = tid & 31;
    const int qt = blockIdx.x, bh = blockIdx.y, b = bh >> 4, h = bh & 15;
    const int mg = w >> 1, ng = w & 1;
    const int lg = lane >> 2, lm = lane & 3;

    const float* qb = q + ((size_t)bh * SEQ + (size_t)qt * TQ) * HD;
    const float* kb = g_kT + (size_t)bh * SEQ * HD;
    float* ab = attn + ((size_t)bh * SEQ + (size_t)qt * TQ) * SEQ;
    const float* bb = bias + ((size_t)h * SEQ + (size_t)qt * TQ) * SEQ;
    const int* mb = mask + ((size_t)b * SEQ + (size_t)qt * TQ) * SEQ;

    // stage Q (pre-scaled, tf32) + stats init + cp.async K(0)
    #pragma unroll
    for (int p = 0; p < 8; p++) {
        int idx = p * 1024 + tid * 4;
        int r = idx >> 7, c = idx & 127;
        float4 qv = *(const float4*)(qb + idx);
        qv.x *= SCALE; qv.y *= SCALE; qv.z *= SCALE; qv.w *= SCALE;
        *(float4*)(S + O_Q + r * STR + c) = t4(qv);
    }
    if (tid < 64) { S[O_MM + tid] = -3.0e38f; S[O_LL + tid] = 0.0f; }
    #pragma unroll
    for (int p = 0; p < 8; p++) {   // K(0): 64 rows x 128 cols
        int idx = p * 1024 + tid * 4;
        int r = idx >> 7, c = idx & 127;
        CP16(smb + (uint32_t)(O_K0 + r * STR + c) * 4u, kb + idx);
    }
    CP_COMMIT;

    // bias/mask(0) register prefetch
    float2 breg[2][4]; int2 mreg[2][4];
    #pragma unroll
    for (int hh = 0; hh < 2; hh++) {
        int r = mg * 16 + hh * 8 + lg;
        const size_t rb = (size_t)r * SEQ + ng * 32 + 2 * lm;
        #pragma unroll
        for (int nt = 0; nt < 4; nt++) {
            breg[hh][nt] = *(const float2*)(bb + rb + nt * 8);
            mreg[hh][nt] = *(const int2*)(mb + rb + nt * 8);
        }
    }
    CP_WAIT0;
    __syncthreads();

    for (int i = 0; i < NCH; i++) {
        const int cur = i & 1;
        // issue K(i+1) into the other buffer (free since sync at end of i-1)
        if (i < NCH - 1) {
            const float* kc2 = kb + (size_t)(i + 1) * TKK * HD;
            const int kbn = cur ? O_K0 : O_K1;
            #pragma unroll
            for (int p = 0; p < 8; p++) {
                int idx = p * 1024 + tid * 4;
                int r = idx >> 7, c = idx & 127;
                CP16(smb + (uint32_t)(kbn + r * STR + c) * 4u, kc2 + idx);
            }
            CP_COMMIT;
        }
        const int kbase = cur ? O_K1 : O_K0;

        float acc[4][4];
        #pragma unroll
        for (int nt = 0; nt < 4; nt++)
            #pragma unroll
            for (int j = 0; j < 4; j++) acc[nt][j] = 0.0f;

        #pragma unroll 4
        for (int ks = 0; ks < 16; ks++) {
            const int kc = ks * 8;
            uint32_t a[4];
            const int r0 = mg * 16 + lg;
            a[0] = SU[O_Q + r0 * STR + kc + lm];
            a[1] = SU[O_Q + (r0 + 8) * STR + kc + lm];
            a[2] = SU[O_Q + r0 * STR + kc + lm + 4];
            a[3] = SU[O_Q + (r0 + 8) * STR + kc + lm + 4];
            #pragma unroll
            for (int nt = 0; nt < 4; nt++) {
                int nr = ng * 32 + nt * 8 + lg;
                uint32_t b0 = SU[kbase + nr * STR + kc + lm];
                uint32_t b1 = SU[kbase + nr * STR + kc + lm + 4];
                mma8(acc[nt], a, b0, b1);
            }
        }
        __syncthreads();   // orders merge(i-1) [w0-1] before partial writes below

        // epilogue: bias+mask, write raw scores, warp-local (max, sumexp)
        #pragma unroll
        for (int hh = 0; hh < 2; hh++) {
            int r = mg * 16 + hh * 8 + lg;
            const size_t rb = (size_t)r * SEQ + (size_t)i * TKK + ng * 32 + 2 * lm;
            float rm = -3.0e38f;
            float sv[8];
            #pragma unroll
            for (int nt = 0; nt < 4; nt++) {
                float s0 = acc[nt][2 * hh] + breg[hh][nt].x;
                float s1 = acc[nt][2 * hh + 1] + breg[hh][nt].y;
                if (mreg[hh][nt].x == 0) s0 = -1.0e9f;
                if (mreg[hh][nt].y == 0) s1 = -1.0e9f;
                *(float2*)(ab + rb + nt * 8) = make_float2(s0, s1);
                sv[2 * nt] = s0; sv[2 * nt + 1] = s1;
                rm = fmaxf(rm, fmaxf(s0, s1));
            }
            rm = fmaxf(rm, __shfl_xor_sync(0xffffffffu, rm, 1));
            rm = fmaxf(rm, __shfl_xor_sync(0xffffffffu, rm, 2));
            float e = 0.0f;
            #pragma unroll
            for (int j = 0; j < 8; j++) e += fexp(sv[j] - rm);
            e += __shfl_xor_sync(0xffffffffu, e, 1);
            e += __shfl_xor_sync(0xffffffffu, e, 2);
            if (lm == 0) {
                S[O_PMX + ng * 64 + r] = rm;
                S[O_PSM + ng * 64 + r] = e;
            }
        }
        // prefetch bias/mask(i+1) (consumed after next MMA — latency hidden)
        if (i < NCH - 1) {
            #pragma unroll
            for (int hh = 0; hh < 2; hh++) {
                int r = mg * 16 + hh * 8 + lg;
                const size_t rb = (size_t)r * SEQ + (size_t)(i + 1) * TKK + ng * 32 + 2 * lm;
                #pragma unroll
                for (int nt = 0; nt < 4; nt++) {
                    breg[hh][nt] = *(const float2*)(bb + rb + nt * 8);
                    mreg[hh][nt] = *(const int2*)(mb + rb + nt * 8);
                }
            }
            CP_WAIT0;   // K(i+1) landed
        }
        __syncthreads();   // partials visible; K(i+1) visible to all

        // merge running stats (tid<64 only; same threads every chunk, no extra
        // barrier — next sync orders partial-buffer reuse)
        if (tid < 64) {
            float m0 = S[O_PMX + tid], m1 = S[O_PMX + 64 + tid];
            float mn = fmaxf(S[O_MM + tid], fmaxf(m0, m1));
            S[O_LL + tid] = S[O_LL + tid] * fexp(S[O_MM + tid] - mn) +
                            S[O_PSM + tid] * fexp(m0 - mn) +
                            S[O_PSM + 64 + tid] * fexp(m1 - mn);
            S[O_MM + tid] = mn;
        }
    }
    if (tid < 64) {
        g_rowM[(size_t)bh * SEQ + qt * TQ + tid] = S[O_MM + tid];
        g_rowL[(size_t)bh * SEQ + qt * TQ + tid] = S[O_LL + tid];
    }
}

// ---------------------------------------------------------------------------
// k2: p = exp(s-m)/l -> final attn; out = P @ V. Raw scores AND V both
// cp.async double-buffered one chunk ahead; 2 syncs per chunk; 2 CTAs/SM.
// ---------------------------------------------------------------------------
__global__ __launch_bounds__(256, 2) void k_out(
    float* __restrict__ attn, float* __restrict__ out) {
    extern __shared__ float S[];
    uint32_t* SU = (uint32_t*)S;
    const uint32_t smb = smem_u32(S);
    const int tid = threadIdx.x, w = tid >> 5, lane = tid & 31;
    const int qt = blockIdx.x, bh = blockIdx.y;
    const int mg = w >> 1, ng = w & 1;
    const int lg = lane >> 2, lm = lane & 3;

    const float* vb = g_vT + (size_t)bh * SEQ * HD;
    float* ab = attn + ((size_t)bh * SEQ + (size_t)qt * TQ) * SEQ;
    float* ob = out + ((size_t)bh * SEQ + (size_t)qt * TQ) * HD;

    if (tid < 64) {
        S[O_M2 + tid] = g_rowM[(size_t)bh * SEQ + qt * TQ + tid];
        S[O_L2 + tid] = 1.0f / g_rowL[(size_t)bh * SEQ + qt * TQ + tid];
    }
    // cp.async Praw(0) + V(0)
    #pragma unroll
    for (int p = 0; p < 4; p++) {   // P: 64 rows x 64 cols
        int idx = p * 1024 + tid * 4;
        int r = idx >> 6, c = idx & 63;
        CP16(smb + (uint32_t)(O_P0 + r * PSTR + c) * 4u,
             ab + (size_t)r * SEQ + c);
    }
    #pragma unroll
    for (int p = 0; p < 8; p++) {   // V: 64 rows x 128 cols
        int idx = p * 1024 + tid * 4;
        int r = idx >> 7, c = idx & 127;
        CP16(smb + (uint32_t)(O_V0 + r * VSTR + c) * 4u, vb + idx);
    }
    CP_COMMIT;

    float acc[8][4];
    #pragma unroll
    for (int nt = 0; nt < 8; nt++)
        #pragma unroll
        for (int j = 0; j < 4; j++) acc[nt][j] = 0.0f;
    __syncthreads();   // stats visible

    for (int i = 0; i < NCH; i++) {
        const int cur = i & 1;
        const int Pb = cur ? O_P1 : O_P0;
        const int Vb = cur ? O_V1 : O_V0;
        if (i < NCH - 1) {  // issue (i+1) into other buffers
            const int Pn = cur ? O_P0 : O_P1;
            const int Vn = cur ? O_V0 : O_V1;
            const float* vc = vb + (size_t)(i + 1) * TKK * HD;
            #pragma unroll
            for (int p = 0; p < 4; p++) {
                int idx = p * 1024 + tid * 4;
                int r = idx >> 6, c = idx & 63;
                CP16(smb + (uint32_t)(Pn + r * PSTR + c) * 4u,
                     ab + (size_t)r * SEQ + (size_t)(i + 1) * TKK + c);
            }
            #pragma unroll
            for (int p = 0; p < 8; p++) {
                int idx = p * 1024 + tid * 4;
                int r = idx >> 7, c = idx & 127;
                CP16(smb + (uint32_t)(Vn + r * VSTR + c) * 4u, vc + idx);
            }
            CP_COMMIT;
            CP_WAIT1;   // group(i) complete (group(i+1) may pend)
        } else {
            CP_WAIT0;
        }
        // normalize own-copied raw P elements: attn write + tf32 in place
        #pragma unroll
        for (int p = 0; p < 4; p++) {
            int idx = p * 1024 + tid * 4;
            int r = idx >> 6, c = idx & 63;
            float4 s4 = *(float4*)(S + Pb + r * PSTR + c);
            float m = S[O_M2 + r], il = S[O_L2 + r];
            float4 p4 = make_float4(fexp(s4.x - m) * il, fexp(s4.y - m) * il,
                                    fexp(s4.z - m) * il, fexp(s4.w - m) * il);
            *(float4*)(ab + (size_t)r * SEQ + (size_t)i * TKK + c) = p4;
            *(float4*)(S + Pb + r * PSTR + c) = t4(p4);
        }
        __syncthreads();   // P(i) tf32 + V(i) visible to all

        #pragma unroll 2
        for (int ks = 0; ks < 8; ks++) {
            const int kc = ks * 8;
            uint32_t a[4];
            const int r0 = mg * 16 + lg;
            a[0] = SU[Pb + r0 * PSTR + kc + lm];
            a[1] = SU[Pb + (r0 + 8) * PSTR + kc + lm];
            a[2] = SU[Pb + r0 * PSTR + kc + lm + 4];
            a[3] = SU[Pb + (r0 + 8) * PSTR + kc + lm + 4];
            #pragma unroll
            for (int nt = 0; nt < 8; nt++) {
                int nc = ng * 64 + nt * 8 + lg;
                uint32_t b0 = SU[Vb + (kc + lm) * VSTR + nc];
                uint32_t b1 = SU[Vb + (kc + lm + 4) * VSTR + nc];
                mma8(acc[nt], a, b0, b1);
            }
        }
        __syncthreads();   // cur buffers free for group(i+2)
    }

    // out epilogue
    #pragma unroll
    for (int hh = 0; hh < 2; hh++) {
        int r = mg * 16 + hh * 8 + lg;
        #pragma unroll
        for (int nt = 0; nt < 8; nt++) {
            int col = ng * 64 + nt * 8 + 2 * lm;
            *(float2*)(ob + (size_t)r * HD + col) =
                make_float2(acc[nt][2 * hh], acc[nt][2 * hh + 1]);
        }
    }
}

extern "C" void kernel_launch(void* const* d_in, const int* in_sizes, int n_in,
                              void* d_out, int out_size) {
    const float* q    = (const float*)d_in[0];
    const float* k    = (const float*)d_in[1];
    const float* v    = (const float*)d_in[2];
    const int*   mask = (const int*)d_in[3];
    const float* bias = (const float*)d_in[4];

    float* out  = (float*)d_out;
    float* attn = out + (size_t)BB * HH * SEQ * HD;

    float* kT; cudaGetSymbolAddress((void**)&kT, g_kT);
    float* vT; cudaGetSymbolAddress((void**)&vT, g_vT);

    cudaFuncSetAttribute(k_scores, cudaFuncAttributeMaxDynamicSharedMemorySize, SMEM1);
    cudaFuncSetAttribute(k_out,    cudaFuncAttributeMaxDynamicSharedMemorySize, SMEM2);

    const int n4 = (BB * HH * SEQ * HD) / 4;
    k_round<<<n4 / 512, 512>>>((const float4*)k, (float4*)kT);
    k_round<<<n4 / 512, 512>>>((const float4*)v, (float4*)vT);

    dim3 grid(SEQ / TQ, BB * HH);
    k_scores<<<grid, 256, SMEM1>>>(q, mask, bias, attn);
    k_out<<<grid, 256, SMEM2>>>(attn, out);
}

// round 10
// speedup vs baseline: 1.5716x; 1.0023x over previous
#include <cuda_runtime.h>
#include <cstdint>
#include <cstddef>

#define BB 2
#define HH 16
#define SEQ 2048
#define HD 128
#define TQ 64            // q rows per block
#define TKK 64           // k positions per chunk
#define NCH (SEQ / TKK)  // 32
#define SCALE 0.08838834764831845f

#define STR 132   // stride (floats) Q/K tiles
#define PSTR 68   // stride (floats) P tile
#define VSTR 136  // stride (floats) V tile

// fused smem map (floats). Phase A region [0,25344) = Q,K0,K1.
// Phase B region [0,26112) = P0,P1,V0,V1 (union; phase A data dead).
// Stats live beyond both: [26112, 26560).
#define O_Q   0                    // [64][132]
#define O_K0  8448
#define O_K1  16896
#define O_P0  0                    // [64][68]
#define O_P1  4352
#define O_V0  8704                 // [64][136]
#define O_V1  17408
#define O_MM  26112                // [64] running max
#define O_LL  26176                // [64] running sum
#define O_IL  26240                // [64] 1/sum
#define O_PMX 26304                // [2][64]
#define O_PSM 26432                // [2][64]
#define SMEM_F (26560)
#define SMEMB (SMEM_F * 4)         // 106240 B -> 2 CTAs/SM

// tf32-pre-rounded K/V copies
__device__ float g_kT[(size_t)BB * HH * SEQ * HD];
__device__ float g_vT[(size_t)BB * HH * SEQ * HD];

__device__ __forceinline__ uint32_t smem_u32(const void* p) {
    uint32_t a;
    asm("{ .reg .u64 t; cvta.to.shared.u64 t, %1; cvt.u32.u64 %0, t; }"
        : "=r"(a) : "l"(p));
    return a;
}
__device__ __forceinline__ float tf32r(float x) {
    uint32_t u; asm("cvt.rna.tf32.f32 %0, %1;" : "=r"(u) : "f"(x));
    return __uint_as_float(u);
}
__device__ __forceinline__ float4 t4(float4 v) {
    return make_float4(tf32r(v.x), tf32r(v.y), tf32r(v.z), tf32r(v.w));
}
// fast exp on fma/alu pipes, |rel err| ~1e-6 for x <= 0
__device__ __forceinline__ float fexp(float x) {
    x = fmaxf(x, -87.0f);
    float y = x * 1.442695041f;
    float t = y + 12582912.0f;
    int   n = __float_as_int(t) - 0x4B400000;
    float f = y - (t - 12582912.0f);
    float p = 1.33335581e-3f;
    p = fmaf(p, f, 9.61812910e-3f);
    p = fmaf(p, f, 5.55041087e-2f);
    p = fmaf(p, f, 2.40226507e-1f);
    p = fmaf(p, f, 6.93147182e-1f);
    p = fmaf(p, f, 1.0f);
    return p * __int_as_float((n + 127) << 23);
}
__device__ __forceinline__ void mma8(float* c, const uint32_t* a, uint32_t b0, uint32_t b1) {
    asm volatile(
        "mma.sync.aligned.m16n8k8.row.col.f32.tf32.tf32.f32 "
        "{%0,%1,%2,%3}, {%4,%5,%6,%7}, {%8,%9}, {%0,%1,%2,%3};"
        : "+f"(c[0]), "+f"(c[1]), "+f"(c[2]), "+f"(c[3])
        : "r"(a[0]), "r"(a[1]), "r"(a[2]), "r"(a[3]), "r"(b0), "r"(b1));
}
#define CP16(dst, src) \
    asm volatile("cp.async.cg.shared.global [%0], [%1], 16;" :: "r"(dst), "l"(src))
#define CP_COMMIT asm volatile("cp.async.commit_group;" ::: "memory")
#define CP_WAIT0 asm volatile("cp.async.wait_group 0;" ::: "memory")
#define CP_WAIT1 asm volatile("cp.async.wait_group 1;" ::: "memory")

__global__ __launch_bounds__(512) void k_round(const float4* __restrict__ src,
                                               float4* __restrict__ dst) {
    int i = blockIdx.x * 512 + threadIdx.x;
    dst[i] = t4(src[i]);
}

// ---------------------------------------------------------------------------
// Fused attention: phase A (scores+stats) then phase B (normalize + P@V),
// same CTA -> raw-score re-read is L2-hot. grid (32 qt, 32 bh), 256 thr.
// ---------------------------------------------------------------------------
__global__ __launch_bounds__(256, 2) void k_fused(
    const float* __restrict__ q, const int* __restrict__ mask,
    const float* __restrict__ bias, float* __restrict__ attn,
    float* __restrict__ out) {
    extern __shared__ float S[];
    uint32_t* SU = (uint32_t*)S;
    const uint32_t smb = smem_u32(S);
    const int tid = threadIdx.x, w = tid >> 5, lane = tid & 31;
    const int qt = blockIdx.x, bh = blockIdx.y, b = bh >> 4, h = bh & 15;
    const int mg = w >> 1, ng = w & 1;
    const int lg = lane >> 2, lm = lane & 3;

    const float* qb = q + ((size_t)bh * SEQ + (size_t)qt * TQ) * HD;
    const float* kb = g_kT + (size_t)bh * SEQ * HD;
    const float* vb = g_vT + (size_t)bh * SEQ * HD;
    float* ab = attn + ((size_t)bh * SEQ + (size_t)qt * TQ) * SEQ;
    const float* bb = bias + ((size_t)h * SEQ + (size_t)qt * TQ) * SEQ;
    const int* mb = mask + ((size_t)b * SEQ + (size_t)qt * TQ) * SEQ;
    float* ob = out + ((size_t)bh * SEQ + (size_t)qt * TQ) * HD;

    // ---------------- phase A: raw scores + online (m, l) ----------------
    #pragma unroll
    for (int p = 0; p < 8; p++) {
        int idx = p * 1024 + tid * 4;
        int r = idx >> 7, c = idx & 127;
        float4 qv = *(const float4*)(qb + idx);
        qv.x *= SCALE; qv.y *= SCALE; qv.z *= SCALE; qv.w *= SCALE;
        *(float4*)(S + O_Q + r * STR + c) = t4(qv);
    }
    if (tid < 64) { S[O_MM + tid] = -3.0e38f; S[O_LL + tid] = 0.0f; }
    #pragma unroll
    for (int p = 0; p < 8; p++) {
        int idx = p * 1024 + tid * 4;
        int r = idx >> 7, c = idx & 127;
        CP16(smb + (uint32_t)(O_K0 + r * STR + c) * 4u, kb + idx);
    }
    CP_COMMIT;

    float2 breg[2][4]; int2 mreg[2][4];
    #pragma unroll
    for (int hh = 0; hh < 2; hh++) {
        int r = mg * 16 + hh * 8 + lg;
        const size_t rb = (size_t)r * SEQ + ng * 32 + 2 * lm;
        #pragma unroll
        for (int nt = 0; nt < 4; nt++) {
            breg[hh][nt] = *(const float2*)(bb + rb + nt * 8);
            mreg[hh][nt] = *(const int2*)(mb + rb + nt * 8);
        }
    }
    CP_WAIT0;
    __syncthreads();

    for (int i = 0; i < NCH; i++) {
        const int cur = i & 1;
        if (i < NCH - 1) {
            const float* kc2 = kb + (size_t)(i + 1) * TKK * HD;
            const int kbn = cur ? O_K0 : O_K1;
            #pragma unroll
            for (int p = 0; p < 8; p++) {
                int idx = p * 1024 + tid * 4;
                int r = idx >> 7, c = idx & 127;
                CP16(smb + (uint32_t)(kbn + r * STR + c) * 4u, kc2 + idx);
            }
            CP_COMMIT;
        }
        const int kbase = cur ? O_K1 : O_K0;

        float acc[4][4];
        #pragma unroll
        for (int nt = 0; nt < 4; nt++)
            #pragma unroll
            for (int j = 0; j < 4; j++) acc[nt][j] = 0.0f;

        #pragma unroll 4
        for (int ks = 0; ks < 16; ks++) {
            const int kc = ks * 8;
            uint32_t a[4];
            const int r0 = mg * 16 + lg;
            a[0] = SU[O_Q + r0 * STR + kc + lm];
            a[1] = SU[O_Q + (r0 + 8) * STR + kc + lm];
            a[2] = SU[O_Q + r0 * STR + kc + lm + 4];
            a[3] = SU[O_Q + (r0 + 8) * STR + kc + lm + 4];
            #pragma unroll
            for (int nt = 0; nt < 4; nt++) {
                int nr = ng * 32 + nt * 8 + lg;
                uint32_t b0 = SU[kbase + nr * STR + kc + lm];
                uint32_t b1 = SU[kbase + nr * STR + kc + lm + 4];
                mma8(acc[nt], a, b0, b1);
            }
        }
        __syncthreads();   // orders merge(i-1) before partial writes

        #pragma unroll
        for (int hh = 0; hh < 2; hh++) {
            int r = mg * 16 + hh * 8 + lg;
            const size_t rb = (size_t)r * SEQ + (size_t)i * TKK + ng * 32 + 2 * lm;
            float rm = -3.0e38f;
            float sv[8];
            #pragma unroll
            for (int nt = 0; nt < 4; nt++) {
                float s0 = acc[nt][2 * hh] + breg[hh][nt].x;
                float s1 = acc[nt][2 * hh + 1] + breg[hh][nt].y;
                if (mreg[hh][nt].x == 0) s0 = -1.0e9f;
                if (mreg[hh][nt].y == 0) s1 = -1.0e9f;
                *(float2*)(ab + rb + nt * 8) = make_float2(s0, s1);
                sv[2 * nt] = s0; sv[2 * nt + 1] = s1;
                rm = fmaxf(rm, fmaxf(s0, s1));
            }
            rm = fmaxf(rm, __shfl_xor_sync(0xffffffffu, rm, 1));
            rm = fmaxf(rm, __shfl_xor_sync(0xffffffffu, rm, 2));
            float e = 0.0f;
            #pragma unroll
            for (int j = 0; j < 8; j++) e += fexp(sv[j] - rm);
            e += __shfl_xor_sync(0xffffffffu, e, 1);
            e += __shfl_xor_sync(0xffffffffu, e, 2);
            if (lm == 0) {
                S[O_PMX + ng * 64 + r] = rm;
                S[O_PSM + ng * 64 + r] = e;
            }
        }
        if (i < NCH - 1) {
            #pragma unroll
            for (int hh = 0; hh < 2; hh++) {
                int r = mg * 16 + hh * 8 + lg;
                const size_t rb = (size_t)r * SEQ + (size_t)(i + 1) * TKK + ng * 32 + 2 * lm;
                #pragma unroll
                for (int nt = 0; nt < 4; nt++) {
                    breg[hh][nt] = *(const float2*)(bb + rb + nt * 8);
                    mreg[hh][nt] = *(const int2*)(mb + rb + nt * 8);
                }
            }
            CP_WAIT0;
        }
        __syncthreads();

        if (tid < 64) {
            float m0 = S[O_PMX + tid], m1 = S[O_PMX + 64 + tid];
            float mn = fmaxf(S[O_MM + tid], fmaxf(m0, m1));
            S[O_LL + tid] = S[O_LL + tid] * fexp(S[O_MM + tid] - mn) +
                            S[O_PSM + tid] * fexp(m0 - mn) +
                            S[O_PSM + 64 + tid] * fexp(m1 - mn);
            S[O_MM + tid] = mn;
        }
    }
    __syncthreads();                 // stats final; phase A smem dead
    if (tid < 64) S[O_IL + tid] = 1.0f / S[O_LL + tid];

    // ---------------- phase B: normalize + P @ V ----------------
    // raw-score reads hit L2 (written moments ago by this CTA)
    #pragma unroll
    for (int p = 0; p < 4; p++) {
        int idx = p * 1024 + tid * 4;
        int r = idx >> 6, c = idx & 63;
        CP16(smb + (uint32_t)(O_P0 + r * PSTR + c) * 4u,
             ab + (size_t)r * SEQ + c);
    }
    #pragma unroll
    for (int p = 0; p < 8; p++) {
        int idx = p * 1024 + tid * 4;
        int r = idx >> 7, c = idx & 127;
        CP16(smb + (uint32_t)(O_V0 + r * VSTR + c) * 4u, vb + idx);
    }
    CP_COMMIT;

    float acc2[8][4];
    #pragma unroll
    for (int nt = 0; nt < 8; nt++)
        #pragma unroll
        for (int j = 0; j < 4; j++) acc2[nt][j] = 0.0f;
    __syncthreads();   // O_IL visible

    for (int i = 0; i < NCH; i++) {
        const int cur = i & 1;
        const int Pb = cur ? O_P1 : O_P0;
        const int Vb = cur ? O_V1 : O_V0;
        if (i < NCH - 1) {
            const int Pn = cur ? O_P0 : O_P1;
            const int Vn = cur ? O_V0 : O_V1;
            const float* vc = vb + (size_t)(i + 1) * TKK * HD;
            #pragma unroll
            for (int p = 0; p < 4; p++) {
                int idx = p * 1024 + tid * 4;
                int r = idx >> 6, c = idx & 63;
                CP16(smb + (uint32_t)(Pn + r * PSTR + c) * 4u,
                     ab + (size_t)r * SEQ + (size_t)(i + 1) * TKK + c);
            }
            #pragma unroll
            for (int p = 0; p < 8; p++) {
                int idx = p * 1024 + tid * 4;
                int r = idx >> 7, c = idx & 127;
                CP16(smb + (uint32_t)(Vn + r * VSTR + c) * 4u, vc + idx);
            }
            CP_COMMIT;
            CP_WAIT1;
        } else {
            CP_WAIT0;
        }
        #pragma unroll
        for (int p = 0; p < 4; p++) {
            int idx = p * 1024 + tid * 4;
            int r = idx >> 6, c = idx & 63;
            float4 s4 = *(float4*)(S + Pb + r * PSTR + c);
            float m = S[O_MM + r], il = S[O_IL + r];
            float4 p4 = make_float4(fexp(s4.x - m) * il, fexp(s4.y - m) * il,
                                    fexp(s4.z - m) * il, fexp(s4.w - m) * il);
            *(float4*)(ab + (size_t)r * SEQ + (size_t)i * TKK + c) = p4;
            *(float4*)(S + Pb + r * PSTR + c) = t4(p4);
        }
        __syncthreads();

        #pragma unroll 2
        for (int ks = 0; ks < 8; ks++) {
            const int kc = ks * 8;
            uint32_t a[4];
            const int r0 = mg * 16 + lg;
            a[0] = SU[Pb + r0 * PSTR + kc + lm];
            a[1] = SU[Pb + (r0 + 8) * PSTR + kc + lm];
            a[2] = SU[Pb + r0 * PSTR + kc + lm + 4];
            a[3] = SU[Pb + (r0 + 8) * PSTR + kc + lm + 4];
            #pragma unroll
            for (int nt = 0; nt < 8; nt++) {
                int nc = ng * 64 + nt * 8 + lg;
                uint32_t b0 = SU[Vb + (kc + lm) * VSTR + nc];
                uint32_t b1 = SU[Vb + (kc + lm + 4) * VSTR + nc];
                mma8(acc2[nt], a, b0, b1);
            }
        }
        __syncthreads();
    }

    #pragma unroll
    for (int hh = 0; hh < 2; hh++) {
        int r = mg * 16 + hh * 8 + lg;
        #pragma unroll
        for (int nt = 0; nt < 8; nt++) {
            int col = ng * 64 + nt * 8 + 2 * lm;
            *(float2*)(ob + (size_t)r * HD + col) =
                make_float2(acc2[nt][2 * hh], acc2[nt][2 * hh + 1]);
        }
    }
}

extern "C" void kernel_launch(void* const* d_in, const int* in_sizes, int n_in,
                              void* d_out, int out_size) {
    const float* q    = (const float*)d_in[0];
    const float* k    = (const float*)d_in[1];
    const float* v    = (const float*)d_in[2];
    const int*   mask = (const int*)d_in[3];
    const float* bias = (const float*)d_in[4];

    float* out  = (float*)d_out;
    float* attn = out + (size_t)BB * HH * SEQ * HD;

    float* kT; cudaGetSymbolAddress((void**)&kT, g_kT);
    float* vT; cudaGetSymbolAddress((void**)&vT, g_vT);

    cudaFuncSetAttribute(k_fused, cudaFuncAttributeMaxDynamicSharedMemorySize, SMEMB);

    const int n4 = (BB * HH * SEQ * HD) / 4;
    k_round<<<n4 / 512, 512>>>((const float4*)k, (float4*)kT);
    k_round<<<n4 / 512, 512>>>((const float4*)v, (float4*)vT);

    dim3 grid(SEQ / TQ, BB * HH);
    k_fused<<<grid, 256, SMEMB>>>(q, mask, bias, attn, out);
}

// round 11
// speedup vs baseline: 1.6439x; 1.0460x over previous
#include <cuda_runtime.h>
#include <cstdint>
#include <cstddef>

#define BB 2
#define HH 16
#define SEQ 2048
#define HD 128
#define TQ 64            // q rows per block
#define TKK 64           // k positions per chunk
#define NCH (SEQ / TKK)  // 32
#define SCALE 0.08838834764831845f

#define STR 132   // stride (floats) Q/K tiles
#define PSTR 68   // stride (floats) P tile
#define VSTR 136  // stride (floats) V tile

// fused smem map (floats); phase A and B regions union.
#define O_Q   0                    // A: [64][132]
#define O_K   8448                 // A: [64][132]
#define O_P0  0                    // B: [64][68]
#define O_P1  4352                 // B: [64][68]
#define O_V   8704                 // B: [64][136]
#define O_MM  17408                // [64] running max
#define O_LL  17472                // [64] running sum
#define O_IL  17536                // [64] 1/sum
#define O_PMX 17600                // [2][64]
#define O_PSM 17728                // [2][64]
#define SMEM_F 17856
#define SMEMB (SMEM_F * 4)         // 71424 B -> 3 CTAs/SM

// tf32-pre-rounded K/V copies
__device__ float g_kT[(size_t)BB * HH * SEQ * HD];
__device__ float g_vT[(size_t)BB * HH * SEQ * HD];

__device__ __forceinline__ uint32_t smem_u32(const void* p) {
    uint32_t a;
    asm("{ .reg .u64 t; cvta.to.shared.u64 t, %1; cvt.u32.u64 %0, t; }"
        : "=r"(a) : "l"(p));
    return a;
}
__device__ __forceinline__ float tf32r(float x) {
    uint32_t u; asm("cvt.rna.tf32.f32 %0, %1;" : "=r"(u) : "f"(x));
    return __uint_as_float(u);
}
__device__ __forceinline__ float4 t4(float4 v) {
    return make_float4(tf32r(v.x), tf32r(v.y), tf32r(v.z), tf32r(v.w));
}
// fast exp on fma/alu pipes, |rel err| ~1e-6 for x <= 0
__device__ __forceinline__ float fexp(float x) {
    x = fmaxf(x, -87.0f);
    float y = x * 1.442695041f;
    float t = y + 12582912.0f;
    int   n = __float_as_int(t) - 0x4B400000;
    float f = y - (t - 12582912.0f);
    float p = 1.33335581e-3f;
    p = fmaf(p, f, 9.61812910e-3f);
    p = fmaf(p, f, 5.55041087e-2f);
    p = fmaf(p, f, 2.40226507e-1f);
    p = fmaf(p, f, 6.93147182e-1f);
    p = fmaf(p, f, 1.0f);
    return p * __int_as_float((n + 127) << 23);
}
__device__ __forceinline__ void mma8(float* c, const uint32_t* a, uint32_t b0, uint32_t b1) {
    asm volatile(
        "mma.sync.aligned.m16n8k8.row.col.f32.tf32.tf32.f32 "
        "{%0,%1,%2,%3}, {%4,%5,%6,%7}, {%8,%9}, {%0,%1,%2,%3};"
        : "+f"(c[0]), "+f"(c[1]), "+f"(c[2]), "+f"(c[3])
        : "r"(a[0]), "r"(a[1]), "r"(a[2]), "r"(a[3]), "r"(b0), "r"(b1));
}
#define CP16(dst, src) \
    asm volatile("cp.async.cg.shared.global [%0], [%1], 16;" :: "r"(dst), "l"(src))
#define CP_COMMIT asm volatile("cp.async.commit_group;" ::: "memory")
#define CP_WAIT0 asm volatile("cp.async.wait_group 0;" ::: "memory")

// pre-round k and v to tf32 (RNA) in one launch
__global__ __launch_bounds__(512) void k_prep(const float4* __restrict__ ksrc,
                                              const float4* __restrict__ vsrc,
                                              float4* __restrict__ kdst,
                                              float4* __restrict__ vdst, int n4) {
    int i = blockIdx.x * 512 + threadIdx.x;
    if (i < n4) kdst[i] = t4(ksrc[i]);
    else        vdst[i - n4] = t4(vsrc[i - n4]);
}

// ---------------------------------------------------------------------------
// Fused attention, 3 CTAs/SM. grid (32 qt, 32 bh), 256 thr (8 warps).
// Phase A: scores+stats (warp tile 16x32). Phase B: normalize + P@V (16x64).
// ---------------------------------------------------------------------------
__global__ __launch_bounds__(256, 3) void k_fused(
    const float* __restrict__ q, const int* __restrict__ mask,
    const float* __restrict__ bias, float* __restrict__ attn,
    float* __restrict__ out) {
    extern __shared__ float S[];
    uint32_t* SU = (uint32_t*)S;
    const uint32_t smb = smem_u32(S);
    const int tid = threadIdx.x, w = tid >> 5, lane = tid & 31;
    const int qt = blockIdx.x, bh = blockIdx.y, b = bh >> 4, h = bh & 15;
    const int mg = w >> 1, ng = w & 1;
    const int lg = lane >> 2, lm = lane & 3;

    const float* qb = q + ((size_t)bh * SEQ + (size_t)qt * TQ) * HD;
    const float* kb = g_kT + (size_t)bh * SEQ * HD;
    const float* vb = g_vT + (size_t)bh * SEQ * HD;
    float* ab = attn + ((size_t)bh * SEQ + (size_t)qt * TQ) * SEQ;
    const float* bb = bias + ((size_t)h * SEQ + (size_t)qt * TQ) * SEQ;
    const int* mb = mask + ((size_t)b * SEQ + (size_t)qt * TQ) * SEQ;
    float* ob = out + ((size_t)bh * SEQ + (size_t)qt * TQ) * HD;

    // ---------------- phase A: raw scores + online (m, l) ----------------
    #pragma unroll
    for (int p = 0; p < 8; p++) {
        int idx = p * 1024 + tid * 4;
        int r = idx >> 7, c = idx & 127;
        float4 qv = *(const float4*)(qb + idx);
        qv.x *= SCALE; qv.y *= SCALE; qv.z *= SCALE; qv.w *= SCALE;
        *(float4*)(S + O_Q + r * STR + c) = t4(qv);
    }
    if (tid < 64) { S[O_MM + tid] = -3.0e38f; S[O_LL + tid] = 0.0f; }
    #pragma unroll
    for (int p = 0; p < 8; p++) {   // K(0)
        int idx = p * 1024 + tid * 4;
        int r = idx >> 7, c = idx & 127;
        CP16(smb + (uint32_t)(O_K + r * STR + c) * 4u, kb + idx);
    }
    CP_COMMIT;

    for (int i = 0; i < NCH; i++) {
        CP_WAIT0;
        __syncthreads();           // K(i) + partials(i-1) visible
        if (tid < 64 && i > 0) {   // merge chunk i-1 stats
            float m0 = S[O_PMX + tid], m1 = S[O_PMX + 64 + tid];
            float mn = fmaxf(S[O_MM + tid], fmaxf(m0, m1));
            S[O_LL + tid] = S[O_LL + tid] * fexp(S[O_MM + tid] - mn) +
                            S[O_PSM + tid] * fexp(m0 - mn) +
                            S[O_PSM + 64 + tid] * fexp(m1 - mn);
            S[O_MM + tid] = mn;
        }

        float acc[4][4];
        #pragma unroll
        for (int nt = 0; nt < 4; nt++)
            #pragma unroll
            for (int j = 0; j < 4; j++) acc[nt][j] = 0.0f;

        #pragma unroll 4
        for (int ks = 0; ks < 16; ks++) {
            const int kc = ks * 8;
            uint32_t a[4];
            const int r0 = mg * 16 + lg;
            a[0] = SU[O_Q + r0 * STR + kc + lm];
            a[1] = SU[O_Q + (r0 + 8) * STR + kc + lm];
            a[2] = SU[O_Q + r0 * STR + kc + lm + 4];
            a[3] = SU[O_Q + (r0 + 8) * STR + kc + lm + 4];
            #pragma unroll
            for (int nt = 0; nt < 4; nt++) {
                int nr = ng * 32 + nt * 8 + lg;
                uint32_t b0 = SU[O_K + nr * STR + kc + lm];
                uint32_t b1 = SU[O_K + nr * STR + kc + lm + 4];
                mma8(acc[nt], a, b0, b1);
            }
        }
        __syncthreads();           // K(i) consumed
        if (i < NCH - 1) {         // K(i+1) load overlaps long epilogue
            const float* kc2 = kb + (size_t)(i + 1) * TKK * HD;
            #pragma unroll
            for (int p = 0; p < 8; p++) {
                int idx = p * 1024 + tid * 4;
                int r = idx >> 7, c = idx & 127;
                CP16(smb + (uint32_t)(O_K + r * STR + c) * 4u, kc2 + idx);
            }
            CP_COMMIT;
        }

        // epilogue: bias+mask (direct loads), raw scores, warp-local (m,l)
        #pragma unroll
        for (int hh = 0; hh < 2; hh++) {
            int r = mg * 16 + hh * 8 + lg;
            const size_t rb = (size_t)r * SEQ + (size_t)i * TKK + ng * 32 + 2 * lm;
            float rm = -3.0e38f;
            float sv[8];
            #pragma unroll
            for (int nt = 0; nt < 4; nt++) {
                float2 bv = *(const float2*)(bb + rb + nt * 8);
                int2 mv = *(const int2*)(mb + rb + nt * 8);
                float s0 = acc[nt][2 * hh] + bv.x;
                float s1 = acc[nt][2 * hh + 1] + bv.y;
                if (mv.x == 0) s0 = -1.0e9f;
                if (mv.y == 0) s1 = -1.0e9f;
                *(float2*)(ab + rb + nt * 8) = make_float2(s0, s1);
                sv[2 * nt] = s0; sv[2 * nt + 1] = s1;
                rm = fmaxf(rm, fmaxf(s0, s1));
            }
            rm = fmaxf(rm, __shfl_xor_sync(0xffffffffu, rm, 1));
            rm = fmaxf(rm, __shfl_xor_sync(0xffffffffu, rm, 2));
            float e = 0.0f;
            #pragma unroll
            for (int j = 0; j < 8; j++) e += fexp(sv[j] - rm);
            e += __shfl_xor_sync(0xffffffffu, e, 1);
            e += __shfl_xor_sync(0xffffffffu, e, 2);
            if (lm == 0) {
                S[O_PMX + ng * 64 + r] = rm;
                S[O_PSM + ng * 64 + r] = e;
            }
        }
    }
    __syncthreads();               // last partials visible; phase A smem dead
    if (tid < 64) {                // final merge + inverse
        float m0 = S[O_PMX + tid], m1 = S[O_PMX + 64 + tid];
        float mn = fmaxf(S[O_MM + tid], fmaxf(m0, m1));
        float ll = S[O_LL + tid] * fexp(S[O_MM + tid] - mn) +
                   S[O_PSM + tid] * fexp(m0 - mn) +
                   S[O_PSM + 64 + tid] * fexp(m1 - mn);
        S[O_MM + tid] = mn;
        S[O_IL + tid] = 1.0f / ll;
    }

    // ---------------- phase B: normalize + P @ V ----------------
    #pragma unroll
    for (int p = 0; p < 4; p++) {   // P(0) raw
        int idx = p * 1024 + tid * 4;
        int r = idx >> 6, c = idx & 63;
        CP16(smb + (uint32_t)(O_P0 + r * PSTR + c) * 4u,
             ab + (size_t)r * SEQ + c);
    }
    #pragma unroll
    for (int p = 0; p < 8; p++) {   // V(0)
        int idx = p * 1024 + tid * 4;
        int r = idx >> 7, c = idx & 127;
        CP16(smb + (uint32_t)(O_V + r * VSTR + c) * 4u, vb + idx);
    }
    CP_COMMIT;

    float acc2[8][4];
    #pragma unroll
    for (int nt = 0; nt < 8; nt++)
        #pragma unroll
        for (int j = 0; j < 4; j++) acc2[nt][j] = 0.0f;

    for (int i = 0; i < NCH; i++) {
        const int Pb = (i & 1) ? O_P1 : O_P0;
        CP_WAIT0;                  // P(i) + V(i) landed (own data visible)
        // normalize own-copied raw P: attn write + tf32 in place
        #pragma unroll
        for (int p = 0; p < 4; p++) {
            int idx = p * 1024 + tid * 4;
            int r = idx >> 6, c = idx & 63;
            float4 s4 = *(float4*)(S + Pb + r * PSTR + c);
            float m = S[O_MM + r], il = S[O_IL + r];
            float4 p4 = make_float4(fexp(s4.x - m) * il, fexp(s4.y - m) * il,
                                    fexp(s4.z - m) * il, fexp(s4.w - m) * il);
            *(float4*)(ab + (size_t)r * SEQ + (size_t)i * TKK + c) = p4;
            *(float4*)(S + Pb + r * PSTR + c) = t4(p4);
        }
        __syncthreads();           // P(i) tf32 + V(i) visible to all
        if (i < NCH - 1) {         // P(i+1) raw load overlaps MMA(i)
            const int Pn = (i & 1) ? O_P0 : O_P1;
            #pragma unroll
            for (int p = 0; p < 4; p++) {
                int idx = p * 1024 + tid * 4;
                int r = idx >> 6, c = idx & 63;
                CP16(smb + (uint32_t)(Pn + r * PSTR + c) * 4u,
                     ab + (size_t)r * SEQ + (size_t)(i + 1) * TKK + c);
            }
            CP_COMMIT;
        }

        #pragma unroll 2
        for (int ks = 0; ks < 8; ks++) {
            const int kc = ks * 8;
            uint32_t a[4];
            const int r0 = mg * 16 + lg;
            a[0] = SU[Pb + r0 * PSTR + kc + lm];
            a[1] = SU[Pb + (r0 + 8) * PSTR + kc + lm];
            a[2] = SU[Pb + r0 * PSTR + kc + lm + 4];
            a[3] = SU[Pb + (r0 + 8) * PSTR + kc + lm + 4];
            #pragma unroll
            for (int nt = 0; nt < 8; nt++) {
                int nc = ng * 64 + nt * 8 + lg;
                uint32_t b0 = SU[O_V + (kc + lm) * VSTR + nc];
                uint32_t b1 = SU[O_V + (kc + lm + 4) * VSTR + nc];
                mma8(acc2[nt], a, b0, b1);
            }
        }
        __syncthreads();           // V(i) consumed
        if (i < NCH - 1) {         // V(i+1) into single buffer
            const float* vc = vb + (size_t)(i + 1) * TKK * HD;
            #pragma unroll
            for (int p = 0; p < 8; p++) {
                int idx = p * 1024 + tid * 4;
                int r = idx >> 7, c = idx & 127;
                CP16(smb + (uint32_t)(O_V + r * VSTR + c) * 4u, vc + idx);
            }
            CP_COMMIT;
        }
    }

    // out epilogue
    #pragma unroll
    for (int hh = 0; hh < 2; hh++) {
        int r = mg * 16 + hh * 8 + lg;
        #pragma unroll
        for (int nt = 0; nt < 8; nt++) {
            int col = ng * 64 + nt * 8 + 2 * lm;
            *(float2*)(ob + (size_t)r * HD + col) =
                make_float2(acc2[nt][2 * hh], acc2[nt][2 * hh + 1]);
        }
    }
}

extern "C" void kernel_launch(void* const* d_in, const int* in_sizes, int n_in,
                              void* d_out, int out_size) {
    const float* q    = (const float*)d_in[0];
    const float* k    = (const float*)d_in[1];
    const float* v    = (const float*)d_in[2];
    const int*   mask = (const int*)d_in[3];
    const float* bias = (const float*)d_in[4];

    float* out  = (float*)d_out;
    float* attn = out + (size_t)BB * HH * SEQ * HD;

    float* kT; cudaGetSymbolAddress((void**)&kT, g_kT);
    float* vT; cudaGetSymbolAddress((void**)&vT, g_vT);

    cudaFuncSetAttribute(k_fused, cudaFuncAttributeMaxDynamicSharedMemorySize, SMEMB);

    const int n4 = (BB * HH * SEQ * HD) / 4;
    k_prep<<<(2 * n4) / 512, 512>>>((const float4*)k, (const float4*)v,
                                    (float4*)kT, (float4*)vT, n4);

    dim3 grid(SEQ / TQ, BB * HH);
    k_fused<<<grid, 256, SMEMB>>>(q, mask, bias, attn, out);
}

// round 13
// speedup vs baseline: 1.6674x; 1.0143x over previous
#include <cuda_runtime.h>
#include <cstdint>
#include <cstddef>

#define BB 2
#define HH 16
#define SEQ 2048
#define HD 128
#define TQ 64            // q rows per block
#define TKK 64           // k positions per chunk
#define NCH (SEQ / TKK)  // 32
#define SCALE 0.08838834764831845f

#define STR 132   // stride (floats) Q/K tiles
#define PSTR 68   // stride (floats) P tile
#define VSTR 136  // stride (floats) V tile

// fused smem map (floats); phase A and B regions union.
#define O_Q   0                    // A: [64][132]
#define O_K   8448                 // A: [64][132]
#define O_P0  0                    // B: [64][68]
#define O_P1  4352                 // B: [64][68]
#define O_V   8704                 // B: [64][136]
#define O_MM  17408                // [64] running max
#define O_LL  17472                // [64] running sum
#define O_IL  17536                // [64] 1/sum
#define O_PMX 17600                // [2][64]
#define O_PSM 17728                // [2][64]
#define O_FAC 17856                // [2][64] per-chunk scale factors
#define SMEM_F 17984
#define SMEMB (SMEM_F * 4)         // 71936 B -> 3 CTAs/SM

// tf32-pre-rounded K/V copies + per-(row, colgroup, chunk) max scratch
__device__ float g_kT[(size_t)BB * HH * SEQ * HD];
__device__ float g_vT[(size_t)BB * HH * SEQ * HD];
__device__ float g_rm[(size_t)BB * HH * 32 * NCH * 128];  // [bh][qt][chunk][g][r]

__device__ __forceinline__ uint32_t smem_u32(const void* p) {
    uint32_t a;
    asm("{ .reg .u64 t; cvta.to.shared.u64 t, %1; cvt.u32.u64 %0, t; }"
        : "=r"(a) : "l"(p));
    return a;
}
__device__ __forceinline__ float tf32r(float x) {
    uint32_t u; asm("cvt.rna.tf32.f32 %0, %1;" : "=r"(u) : "f"(x));
    return __uint_as_float(u);
}
__device__ __forceinline__ float4 t4(float4 v) {
    return make_float4(tf32r(v.x), tf32r(v.y), tf32r(v.z), tf32r(v.w));
}
// fast exp on fma/alu pipes, |rel err| ~1e-6 for x <= 0
__device__ __forceinline__ float fexp(float x) {
    x = fmaxf(x, -87.0f);
    float y = x * 1.442695041f;
    float t = y + 12582912.0f;
    int   n = __float_as_int(t) - 0x4B400000;
    float f = y - (t - 12582912.0f);
    float p = 1.33335581e-3f;
    p = fmaf(p, f, 9.61812910e-3f);
    p = fmaf(p, f, 5.55041087e-2f);
    p = fmaf(p, f, 2.40226507e-1f);
    p = fmaf(p, f, 6.93147182e-1f);
    p = fmaf(p, f, 1.0f);
    return p * __int_as_float((n + 127) << 23);
}
__device__ __forceinline__ void mma8(float* c, const uint32_t* a, uint32_t b0, uint32_t b1) {
    asm volatile(
        "mma.sync.aligned.m16n8k8.row.col.f32.tf32.tf32.f32 "
        "{%0,%1,%2,%3}, {%4,%5,%6,%7}, {%8,%9}, {%0,%1,%2,%3};"
        : "+f"(c[0]), "+f"(c[1]), "+f"(c[2]), "+f"(c[3])
        : "r"(a[0]), "r"(a[1]), "r"(a[2]), "r"(a[3]), "r"(b0), "r"(b1));
}
#define CP16(dst, src) \
    asm volatile("cp.async.cg.shared.global [%0], [%1], 16;" :: "r"(dst), "l"(src))
#define CP_COMMIT asm volatile("cp.async.commit_group;" ::: "memory")
#define CP_WAIT0 asm volatile("cp.async.wait_group 0;" ::: "memory")

// pre-round k and v to tf32 (RNA) in one launch
__global__ __launch_bounds__(512) void k_prep(const float4* __restrict__ ksrc,
                                              const float4* __restrict__ vsrc,
                                              float4* __restrict__ kdst,
                                              float4* __restrict__ vdst, int n4) {
    int i = blockIdx.x * 512 + threadIdx.x;
    if (i < n4) kdst[i] = t4(ksrc[i]);
    else        vdst[i - n4] = t4(vsrc[i - n4]);
}

// ---------------------------------------------------------------------------
// Fused attention, 3 CTAs/SM. grid (32 qt, 32 bh), 256 thr (8 warps).
// Phase A: scores -> store e=exp(s-rm) + stats + rm scratch.
// Phase B: attn = e * fac (one mul/elt) + P @ V.
// ---------------------------------------------------------------------------
__global__ __launch_bounds__(256, 3) void k_fused(
    const float* __restrict__ q, const int* __restrict__ mask,
    const float* __restrict__ bias, float* __restrict__ attn,
    float* __restrict__ out) {
    extern __shared__ float S[];
    uint32_t* SU = (uint32_t*)S;
    const uint32_t smb = smem_u32(S);
    const int tid = threadIdx.x, w = tid >> 5, lane = tid & 31;
    const int qt = blockIdx.x, bh = blockIdx.y, b = bh >> 4, h = bh & 15;
    const int mg = w >> 1, ng = w & 1;
    const int lg = lane >> 2, lm = lane & 3;

    const float* qb = q + ((size_t)bh * SEQ + (size_t)qt * TQ) * HD;
    const float* kb = g_kT + (size_t)bh * SEQ * HD;
    const float* vb = g_vT + (size_t)bh * SEQ * HD;
    float* ab = attn + ((size_t)bh * SEQ + (size_t)qt * TQ) * SEQ;
    const float* bb = bias + ((size_t)h * SEQ + (size_t)qt * TQ) * SEQ;
    const int* mb = mask + ((size_t)b * SEQ + (size_t)qt * TQ) * SEQ;
    float* ob = out + ((size_t)bh * SEQ + (size_t)qt * TQ) * HD;
    const size_t grmb = (size_t)(bh * 32 + qt) * (NCH * 128);

    // ---------------- phase A: e-scores + online (m, l) ----------------
    #pragma unroll
    for (int p = 0; p < 8; p++) {
        int idx = p * 1024 + tid * 4;
        int r = idx >> 7, c = idx & 127;
        float4 qv = *(const float4*)(qb + idx);
        qv.x *= SCALE; qv.y *= SCALE; qv.z *= SCALE; qv.w *= SCALE;
        *(float4*)(S + O_Q + r * STR + c) = t4(qv);
    }
    if (tid < 64) { S[O_MM + tid] = -3.0e38f; S[O_LL + tid] = 0.0f; }
    #pragma unroll
    for (int p = 0; p < 8; p++) {   // K(0)
        int idx = p * 1024 + tid * 4;
        int r = idx >> 7, c = idx & 127;
        CP16(smb + (uint32_t)(O_K + r * STR + c) * 4u, kb + idx);
    }
    CP_COMMIT;

    for (int i = 0; i < NCH; i++) {
        CP_WAIT0;
        __syncthreads();           // K(i) + partials(i-1) visible
        if (tid < 64 && i > 0) {   // merge chunk i-1 stats
            float m0 = S[O_PMX + tid], m1 = S[O_PMX + 64 + tid];
            float mn = fmaxf(S[O_MM + tid], fmaxf(m0, m1));
            S[O_LL + tid] = S[O_LL + tid] * fexp(S[O_MM + tid] - mn) +
                            S[O_PSM + tid] * fexp(m0 - mn) +
                            S[O_PSM + 64 + tid] * fexp(m1 - mn);
            S[O_MM + tid] = mn;
        }

        float acc[4][4];
        #pragma unroll
        for (int nt = 0; nt < 4; nt++)
            #pragma unroll
            for (int j = 0; j < 4; j++) acc[nt][j] = 0.0f;

        #pragma unroll 4
        for (int ks = 0; ks < 16; ks++) {
            const int kc = ks * 8;
            uint32_t a[4];
            const int r0 = mg * 16 + lg;
            a[0] = SU[O_Q + r0 * STR + kc + lm];
            a[1] = SU[O_Q + (r0 + 8) * STR + kc + lm];
            a[2] = SU[O_Q + r0 * STR + kc + lm + 4];
            a[3] = SU[O_Q + (r0 + 8) * STR + kc + lm + 4];
            #pragma unroll
            for (int nt = 0; nt < 4; nt++) {
                int nr = ng * 32 + nt * 8 + lg;
                uint32_t b0 = SU[O_K + nr * STR + kc + lm];
                uint32_t b1 = SU[O_K + nr * STR + kc + lm + 4];
                mma8(acc[nt], a, b0, b1);
            }
        }
        __syncthreads();           // K(i) consumed
        if (i < NCH - 1) {         // K(i+1) load overlaps long epilogue
            const float* kc2 = kb + (size_t)(i + 1) * TKK * HD;
            #pragma unroll
            for (int p = 0; p < 8; p++) {
                int idx = p * 1024 + tid * 4;
                int r = idx >> 7, c = idx & 127;
                CP16(smb + (uint32_t)(O_K + r * STR + c) * 4u, kc2 + idx);
            }
            CP_COMMIT;
        }

        // epilogue: bias+mask, rm, store e=exp(s-rm), warp-local sums
        #pragma unroll
        for (int hh = 0; hh < 2; hh++) {
            int r = mg * 16 + hh * 8 + lg;
            const size_t rb = (size_t)r * SEQ + (size_t)i * TKK + ng * 32 + 2 * lm;
            float rm = -3.0e38f;
            float sv[8];
            #pragma unroll
            for (int nt = 0; nt < 4; nt++) {
                float2 bv = *(const float2*)(bb + rb + nt * 8);
                int2 mv = *(const int2*)(mb + rb + nt * 8);
                float s0 = acc[nt][2 * hh] + bv.x;
                float s1 = acc[nt][2 * hh + 1] + bv.y;
                if (mv.x == 0) s0 = -1.0e9f;
                if (mv.y == 0) s1 = -1.0e9f;
                sv[2 * nt] = s0; sv[2 * nt + 1] = s1;
                rm = fmaxf(rm, fmaxf(s0, s1));
            }
            rm = fmaxf(rm, __shfl_xor_sync(0xffffffffu, rm, 1));
            rm = fmaxf(rm, __shfl_xor_sync(0xffffffffu, rm, 2));
            float e = 0.0f;
            #pragma unroll
            for (int j = 0; j < 8; j++) { sv[j] = fexp(sv[j] - rm); e += sv[j]; }
            #pragma unroll
            for (int nt = 0; nt < 4; nt++)
                *(float2*)(ab + rb + nt * 8) = make_float2(sv[2 * nt], sv[2 * nt + 1]);
            e += __shfl_xor_sync(0xffffffffu, e, 1);
            e += __shfl_xor_sync(0xffffffffu, e, 2);
            if (lm == 0) {
                S[O_PMX + ng * 64 + r] = rm;
                S[O_PSM + ng * 64 + r] = e;
                g_rm[grmb + (size_t)i * 128 + ng * 64 + r] = rm;
            }
        }
    }
    __syncthreads();               // last partials visible; phase A smem dead
    if (tid < 64) {                // final merge + inverse
        float m0 = S[O_PMX + tid], m1 = S[O_PMX + 64 + tid];
        float mn = fmaxf(S[O_MM + tid], fmaxf(m0, m1));
        float ll = S[O_LL + tid] * fexp(S[O_MM + tid] - mn) +
                   S[O_PSM + tid] * fexp(m0 - mn) +
                   S[O_PSM + 64 + tid] * fexp(m1 - mn);
        S[O_MM + tid] = mn;
        S[O_IL + tid] = 1.0f / ll;
    }

    // ---------------- phase B: attn = e*fac + P @ V ----------------
    #pragma unroll
    for (int p = 0; p < 4; p++) {   // P(0) (e-values)
        int idx = p * 1024 + tid * 4;
        int r = idx >> 6, c = idx & 63;
        CP16(smb + (uint32_t)(O_P0 + r * PSTR + c) * 4u,
             ab + (size_t)r * SEQ + c);
    }
    #pragma unroll
    for (int p = 0; p < 8; p++) {   // V(0)
        int idx = p * 1024 + tid * 4;
        int r = idx >> 7, c = idx & 127;
        CP16(smb + (uint32_t)(O_V + r * VSTR + c) * 4u, vb + idx);
    }
    CP_COMMIT;
    __syncthreads();               // MM/IL visible

    float rmreg = 0.0f;
    if (tid < 128) {               // factors for chunk 0 + prefetch rm(1)
        int rr = tid & 63;
        float rm0 = g_rm[grmb + tid];
        S[O_FAC + tid] = fexp(rm0 - S[O_MM + rr]) * S[O_IL + rr];
        rmreg = g_rm[grmb + 128 + tid];
    }

    float acc2[8][4];
    #pragma unroll
    for (int nt = 0; nt < 8; nt++)
        #pragma unroll
        for (int j = 0; j < 4; j++) acc2[nt][j] = 0.0f;
    __syncthreads();               // FAC(0) visible

    for (int i = 0; i < NCH; i++) {
        const int Pb = (i & 1) ? O_P1 : O_P0;
        CP_WAIT0;                  // P(i) + V(i) landed (own data visible)
        // normalize: attn write + tf32 in place (one mul per element)
        #pragma unroll
        for (int p = 0; p < 4; p++) {
            int idx = p * 1024 + tid * 4;
            int r = idx >> 6, c = idx & 63;
            float4 e4 = *(float4*)(S + Pb + r * PSTR + c);
            float f = S[O_FAC + ((c >> 5) << 6) + r];
            float4 p4 = make_float4(e4.x * f, e4.y * f, e4.z * f, e4.w * f);
            *(float4*)(ab + (size_t)r * SEQ + (size_t)i * TKK + c) = p4;
            *(float4*)(S + Pb + r * PSTR + c) = t4(p4);
        }
        __syncthreads();           // staging done; FAC(i) consumed
        if (i < NCH - 1) {         // P(i+1) load + FAC(i+1) overlap MMA(i)
            const int Pn = (i & 1) ? O_P0 : O_P1;
            #pragma unroll
            for (int p = 0; p < 4; p++) {
                int idx = p * 1024 + tid * 4;
                int r = idx >> 6, c = idx & 63;
                CP16(smb + (uint32_t)(Pn + r * PSTR + c) * 4u,
                     ab + (size_t)r * SEQ + (size_t)(i + 1) * TKK + c);
            }
            CP_COMMIT;
            if (tid < 128) {
                int rr = tid & 63;
                S[O_FAC + tid] = fexp(rmreg - S[O_MM + rr]) * S[O_IL + rr];
                if (i < NCH - 2) rmreg = g_rm[grmb + (size_t)(i + 2) * 128 + tid];
            }
        }

        #pragma unroll 2
        for (int ks = 0; ks < 8; ks++) {
            const int kc = ks * 8;
            uint32_t a[4];
            const int r0 = mg * 16 + lg;
            a[0] = SU[Pb + r0 * PSTR + kc + lm];
            a[1] = SU[Pb + (r0 + 8) * PSTR + kc + lm];
            a[2] = SU[Pb + r0 * PSTR + kc + lm + 4];
            a[3] = SU[Pb + (r0 + 8) * PSTR + kc + lm + 4];
            #pragma unroll
            for (int nt = 0; nt < 8; nt++) {
                int nc = ng * 64 + nt * 8 + lg;
                uint32_t b0 = SU[O_V + (kc + lm) * VSTR + nc];
                uint32_t b1 = SU[O_V + (kc + lm + 4) * VSTR + nc];
                mma8(acc2[nt], a, b0, b1);
            }
        }
        __syncthreads();           // V(i) consumed; FAC(i+1) visible
        if (i < NCH - 1) {         // V(i+1) into single buffer
            const float* vc = vb + (size_t)(i + 1) * TKK * HD;
            #pragma unroll
            for (int p = 0; p < 8; p++) {
                int idx = p * 1024 + tid * 4;
                int r = idx >> 7, c = idx & 127;
                CP16(smb + (uint32_t)(O_V + r * VSTR + c) * 4u, vc + idx);
            }
            CP_COMMIT;
        }
    }

    // out epilogue
    #pragma unroll
    for (int hh = 0; hh < 2; hh++) {
        int r = mg * 16 + hh * 8 + lg;
        #pragma unroll
        for (int nt = 0; nt < 8; nt++) {
            int col = ng * 64 + nt * 8 + 2 * lm;
            *(float2*)(ob + (size_t)r * HD + col) =
                make_float2(acc2[nt][2 * hh], acc2[nt][2 * hh + 1]);
        }
    }
}

extern "C" void kernel_launch(void* const* d_in, const int* in_sizes, int n_in,
                              void* d_out, int out_size) {
    const float* q    = (const float*)d_in[0];
    const float* k    = (const float*)d_in[1];
    const float* v    = (const float*)d_in[2];
    const int*   mask = (const int*)d_in[3];
    const float* bias = (const float*)d_in[4];

    float* out  = (float*)d_out;
    float* attn = out + (size_t)BB * HH * SEQ * HD;

    float* kT; cudaGetSymbolAddress((void**)&kT, g_kT);
    float* vT; cudaGetSymbolAddress((void**)&vT, g_vT);

    cudaFuncSetAttribute(k_fused, cudaFuncAttributeMaxDynamicSharedMemorySize, SMEMB);

    const int n4 = (BB * HH * SEQ * HD) / 4;
    k_prep<<<(2 * n4) / 512, 512>>>((const float4*)k, (const float4*)v,
                                    (float4*)kT, (float4*)vT, n4);

    dim3 grid(SEQ / TQ, BB * HH);
    k_fused<<<grid, 256, SMEMB>>>(q, mask, bias, attn, out);
}

// round 14
// speedup vs baseline: 1.7696x; 1.0613x over previous
#include <cuda_runtime.h>
#include <cstdint>
#include <cstddef>

#define BB 2
#define HH 16
#define SEQ 2048
#define HD 128
#define TQ 64            // q rows per block
#define TKK 64           // k positions per chunk
#define NCH (SEQ / TKK)  // 32
#define SCALE 0.08838834764831845f

#define STR 132   // stride (floats) Q/K tiles
#define PSTR 68   // stride (floats) P tile
#define VSTR 136  // stride (floats) V tile

// fused smem map (floats); phase A and B regions union.
#define O_Q   0                    // A: [64][132]
#define O_K   8448                 // A: [64][132]
#define O_P0  0                    // B: [64][68]
#define O_P1  4352                 // B: [64][68]
#define O_V   8704                 // B: [64][136]
#define O_MM  17408                // [64] running max
#define O_LL  17472                // [64] running sum
#define O_IL  17536                // [64] 1/sum
#define O_PMX 17600                // [2][64]
#define O_PSM 17728                // [2][64]
#define O_FAC 17856                // [2][64] per-chunk scale factors
#define SMEM_F 17984
#define SMEMB (SMEM_F * 4)         // 71936 B -> 3 CTAs/SM

#define NMW (BB * SEQ * (SEQ / 32))   // mask words: 262144

// tf32-pre-rounded K/V copies + rm scratch + packed mask bits
__device__ float g_kT[(size_t)BB * HH * SEQ * HD];
__device__ float g_vT[(size_t)BB * HH * SEQ * HD];
__device__ float g_rm[(size_t)BB * HH * 32 * NCH * 128];
__device__ uint32_t g_mk[NMW];     // [b][qrow][kcol/32], bit = kcol%32

__device__ __forceinline__ uint32_t smem_u32(const void* p) {
    uint32_t a;
    asm("{ .reg .u64 t; cvta.to.shared.u64 t, %1; cvt.u32.u64 %0, t; }"
        : "=r"(a) : "l"(p));
    return a;
}
__device__ __forceinline__ float tf32r(float x) {
    uint32_t u; asm("cvt.rna.tf32.f32 %0, %1;" : "=r"(u) : "f"(x));
    return __uint_as_float(u);
}
__device__ __forceinline__ float4 t4(float4 v) {
    return make_float4(tf32r(v.x), tf32r(v.y), tf32r(v.z), tf32r(v.w));
}
// fast exp on fma/alu pipes, |rel err| ~1e-6 for x <= 0
__device__ __forceinline__ float fexp(float x) {
    x = fmaxf(x, -87.0f);
    float y = x * 1.442695041f;
    float t = y + 12582912.0f;
    int   n = __float_as_int(t) - 0x4B400000;
    float f = y - (t - 12582912.0f);
    float p = 1.33335581e-3f;
    p = fmaf(p, f, 9.61812910e-3f);
    p = fmaf(p, f, 5.55041087e-2f);
    p = fmaf(p, f, 2.40226507e-1f);
    p = fmaf(p, f, 6.93147182e-1f);
    p = fmaf(p, f, 1.0f);
    return p * __int_as_float((n + 127) << 23);
}
__device__ __forceinline__ void mma8(float* c, const uint32_t* a, uint32_t b0, uint32_t b1) {
    asm volatile(
        "mma.sync.aligned.m16n8k8.row.col.f32.tf32.tf32.f32 "
        "{%0,%1,%2,%3}, {%4,%5,%6,%7}, {%8,%9}, {%0,%1,%2,%3};"
        : "+f"(c[0]), "+f"(c[1]), "+f"(c[2]), "+f"(c[3])
        : "r"(a[0]), "r"(a[1]), "r"(a[2]), "r"(a[3]), "r"(b0), "r"(b1));
}
#define CP16(dst, src) \
    asm volatile("cp.async.cg.shared.global [%0], [%1], 16;" :: "r"(dst), "l"(src))
#define CP_COMMIT asm volatile("cp.async.commit_group;" ::: "memory")
#define CP_WAIT0 asm volatile("cp.async.wait_group 0;" ::: "memory")

// k_prep: tf32-round K and V; pack mask into bits. One launch.
__global__ __launch_bounds__(512) void k_prep(const float4* __restrict__ ksrc,
                                              const float4* __restrict__ vsrc,
                                              const int* __restrict__ msrc,
                                              float4* __restrict__ kdst,
                                              float4* __restrict__ vdst, int n4) {
    int i = blockIdx.x * 512 + threadIdx.x;
    if (i < n4) {
        kdst[i] = t4(ksrc[i]);
    } else if (i < 2 * n4) {
        vdst[i - n4] = t4(vsrc[i - n4]);
    } else if (i < 2 * n4 + NMW) {
        int j = i - 2 * n4;
        const int4* mp = (const int4*)(msrc + (size_t)j * 32);
        uint32_t bits = 0;
        #pragma unroll
        for (int p = 0; p < 8; p++) {
            int4 m4 = mp[p];
            bits |= (uint32_t)(m4.x != 0) << (4 * p);
            bits |= (uint32_t)(m4.y != 0) << (4 * p + 1);
            bits |= (uint32_t)(m4.z != 0) << (4 * p + 2);
            bits |= (uint32_t)(m4.w != 0) << (4 * p + 3);
        }
        g_mk[j] = bits;
    }
}

// ---------------------------------------------------------------------------
// Fused attention, 3 CTAs/SM. grid (32 qt, 32 bh), 256 thr (8 warps).
// Phase A: scores -> store e=exp(s-rm) + stats + rm scratch (mask from bits).
// Phase B: attn = e * fac + P @ V.
// ---------------------------------------------------------------------------
__global__ __launch_bounds__(256, 3) void k_fused(
    const float* __restrict__ q,
    const float* __restrict__ bias, float* __restrict__ attn,
    float* __restrict__ out) {
    extern __shared__ float S[];
    uint32_t* SU = (uint32_t*)S;
    const uint32_t smb = smem_u32(S);
    const int tid = threadIdx.x, w = tid >> 5, lane = tid & 31;
    const int qt = blockIdx.x, bh = blockIdx.y, b = bh >> 4, h = bh & 15;
    const int mg = w >> 1, ng = w & 1;
    const int lg = lane >> 2, lm = lane & 3;

    const float* qb = q + ((size_t)bh * SEQ + (size_t)qt * TQ) * HD;
    const float* kb = g_kT + (size_t)bh * SEQ * HD;
    const float* vb = g_vT + (size_t)bh * SEQ * HD;
    float* ab = attn + ((size_t)bh * SEQ + (size_t)qt * TQ) * SEQ;
    const float* bb = bias + ((size_t)h * SEQ + (size_t)qt * TQ) * SEQ;
    const uint32_t* mkb = g_mk + ((size_t)b * SEQ + (size_t)qt * TQ) * (SEQ / 32);
    float* ob = out + ((size_t)bh * SEQ + (size_t)qt * TQ) * HD;
    const size_t grmb = (size_t)(bh * 32 + qt) * (NCH * 128);

    // ---------------- phase A: e-scores + online (m, l) ----------------
    #pragma unroll
    for (int p = 0; p < 8; p++) {
        int idx = p * 1024 + tid * 4;
        int r = idx >> 7, c = idx & 127;
        float4 qv = *(const float4*)(qb + idx);
        qv.x *= SCALE; qv.y *= SCALE; qv.z *= SCALE; qv.w *= SCALE;
        *(float4*)(S + O_Q + r * STR + c) = t4(qv);
    }
    if (tid < 64) { S[O_MM + tid] = -3.0e38f; S[O_LL + tid] = 0.0f; }
    #pragma unroll
    for (int p = 0; p < 8; p++) {   // K(0)
        int idx = p * 1024 + tid * 4;
        int r = idx >> 7, c = idx & 127;
        CP16(smb + (uint32_t)(O_K + r * STR + c) * 4u, kb + idx);
    }
    CP_COMMIT;

    for (int i = 0; i < NCH; i++) {
        CP_WAIT0;
        __syncthreads();           // K(i) + partials(i-1) visible
        if (tid < 64 && i > 0) {   // merge chunk i-1 stats
            float m0 = S[O_PMX + tid], m1 = S[O_PMX + 64 + tid];
            float mn = fmaxf(S[O_MM + tid], fmaxf(m0, m1));
            S[O_LL + tid] = S[O_LL + tid] * fexp(S[O_MM + tid] - mn) +
                            S[O_PSM + tid] * fexp(m0 - mn) +
                            S[O_PSM + 64 + tid] * fexp(m1 - mn);
            S[O_MM + tid] = mn;
        }

        float acc[4][4];
        #pragma unroll
        for (int nt = 0; nt < 4; nt++)
            #pragma unroll
            for (int j = 0; j < 4; j++) acc[nt][j] = 0.0f;

        #pragma unroll 4
        for (int ks = 0; ks < 16; ks++) {
            const int kc = ks * 8;
            uint32_t a[4];
            const int r0 = mg * 16 + lg;
            a[0] = SU[O_Q + r0 * STR + kc + lm];
            a[1] = SU[O_Q + (r0 + 8) * STR + kc + lm];
            a[2] = SU[O_Q + r0 * STR + kc + lm + 4];
            a[3] = SU[O_Q + (r0 + 8) * STR + kc + lm + 4];
            #pragma unroll
            for (int nt = 0; nt < 4; nt++) {
                int nr = ng * 32 + nt * 8 + lg;
                uint32_t b0 = SU[O_K + nr * STR + kc + lm];
                uint32_t b1 = SU[O_K + nr * STR + kc + lm + 4];
                mma8(acc[nt], a, b0, b1);
            }
        }
        __syncthreads();           // K(i) consumed
        if (i < NCH - 1) {         // K(i+1) load overlaps long epilogue
            const float* kc2 = kb + (size_t)(i + 1) * TKK * HD;
            #pragma unroll
            for (int p = 0; p < 8; p++) {
                int idx = p * 1024 + tid * 4;
                int r = idx >> 7, c = idx & 127;
                CP16(smb + (uint32_t)(O_K + r * STR + c) * 4u, kc2 + idx);
            }
            CP_COMMIT;
        }

        // epilogue: bias + mask bits, rm, store e=exp(s-rm), warp-local sums
        #pragma unroll
        for (int hh = 0; hh < 2; hh++) {
            int r = mg * 16 + hh * 8 + lg;
            const size_t rb = (size_t)r * SEQ + (size_t)i * TKK + ng * 32 + 2 * lm;
            const uint32_t mw = mkb[(size_t)r * (SEQ / 32) + i * 2 + ng];
            float rm = -3.0e38f;
            float sv[8];
            #pragma unroll
            for (int nt = 0; nt < 4; nt++) {
                float2 bv = *(const float2*)(bb + rb + nt * 8);
                float s0 = acc[nt][2 * hh] + bv.x;
                float s1 = acc[nt][2 * hh + 1] + bv.y;
                if (!((mw >> (nt * 8 + 2 * lm)) & 1u)) s0 = -1.0e9f;
                if (!((mw >> (nt * 8 + 2 * lm + 1)) & 1u)) s1 = -1.0e9f;
                sv[2 * nt] = s0; sv[2 * nt + 1] = s1;
                rm = fmaxf(rm, fmaxf(s0, s1));
            }
            rm = fmaxf(rm, __shfl_xor_sync(0xffffffffu, rm, 1));
            rm = fmaxf(rm, __shfl_xor_sync(0xffffffffu, rm, 2));
            float e = 0.0f;
            #pragma unroll
            for (int j = 0; j < 8; j++) { sv[j] = fexp(sv[j] - rm); e += sv[j]; }
            #pragma unroll
            for (int nt = 0; nt < 4; nt++)
                *(float2*)(ab + rb + nt * 8) = make_float2(sv[2 * nt], sv[2 * nt + 1]);
            e += __shfl_xor_sync(0xffffffffu, e, 1);
            e += __shfl_xor_sync(0xffffffffu, e, 2);
            if (lm == 0) {
                S[O_PMX + ng * 64 + r] = rm;
                S[O_PSM + ng * 64 + r] = e;
                g_rm[grmb + (size_t)i * 128 + ng * 64 + r] = rm;
            }
        }
    }
    __syncthreads();               // last partials visible; phase A smem dead
    if (tid < 64) {                // final merge + inverse
        float m0 = S[O_PMX + tid], m1 = S[O_PMX + 64 + tid];
        float mn = fmaxf(S[O_MM + tid], fmaxf(m0, m1));
        float ll = S[O_LL + tid] * fexp(S[O_MM + tid] - mn) +
                   S[O_PSM + tid] * fexp(m0 - mn) +
                   S[O_PSM + 64 + tid] * fexp(m1 - mn);
        S[O_MM + tid] = mn;
        S[O_IL + tid] = 1.0f / ll;
    }

    // ---------------- phase B: attn = e*fac + P @ V ----------------
    #pragma unroll
    for (int p = 0; p < 4; p++) {   // P(0) (e-values)
        int idx = p * 1024 + tid * 4;
        int r = idx >> 6, c = idx & 63;
        CP16(smb + (uint32_t)(O_P0 + r * PSTR + c) * 4u,
             ab + (size_t)r * SEQ + c);
    }
    #pragma unroll
    for (int p = 0; p < 8; p++) {   // V(0)
        int idx = p * 1024 + tid * 4;
        int r = idx >> 7, c = idx & 127;
        CP16(smb + (uint32_t)(O_V + r * VSTR + c) * 4u, vb + idx);
    }
    CP_COMMIT;
    __syncthreads();               // MM/IL visible

    float rmreg = 0.0f;
    if (tid < 128) {               // factors for chunk 0 + prefetch rm(1)
        int rr = tid & 63;
        float rm0 = g_rm[grmb + tid];
        S[O_FAC + tid] = fexp(rm0 - S[O_MM + rr]) * S[O_IL + rr];
        rmreg = g_rm[grmb + 128 + tid];
    }

    float acc2[8][4];
    #pragma unroll
    for (int nt = 0; nt < 8; nt++)
        #pragma unroll
        for (int j = 0; j < 4; j++) acc2[nt][j] = 0.0f;
    __syncthreads();               // FAC(0) visible

    for (int i = 0; i < NCH; i++) {
        const int Pb = (i & 1) ? O_P1 : O_P0;
        CP_WAIT0;                  // P(i) + V(i) landed (own data visible)
        #pragma unroll
        for (int p = 0; p < 4; p++) {
            int idx = p * 1024 + tid * 4;
            int r = idx >> 6, c = idx & 63;
            float4 e4 = *(float4*)(S + Pb + r * PSTR + c);
            float f = S[O_FAC + ((c >> 5) << 6) + r];
            float4 p4 = make_float4(e4.x * f, e4.y * f, e4.z * f, e4.w * f);
            *(float4*)(ab + (size_t)r * SEQ + (size_t)i * TKK + c) = p4;
            *(float4*)(S + Pb + r * PSTR + c) = t4(p4);
        }
        __syncthreads();           // staging done; FAC(i) consumed
        if (i < NCH - 1) {         // P(i+1) load + FAC(i+1) overlap MMA(i)
            const int Pn = (i & 1) ? O_P0 : O_P1;
            #pragma unroll
            for (int p = 0; p < 4; p++) {
                int idx = p * 1024 + tid * 4;
                int r = idx >> 6, c = idx & 63;
                CP16(smb + (uint32_t)(Pn + r * PSTR + c) * 4u,
                     ab + (size_t)r * SEQ + (size_t)(i + 1) * TKK + c);
            }
            CP_COMMIT;
            if (tid < 128) {
                int rr = tid & 63;
                S[O_FAC + tid] = fexp(rmreg - S[O_MM + rr]) * S[O_IL + rr];
                if (i < NCH - 2) rmreg = g_rm[grmb + (size_t)(i + 2) * 128 + tid];
            }
        }

        #pragma unroll 2
        for (int ks = 0; ks < 8; ks++) {
            const int kc = ks * 8;
            uint32_t a[4];
            const int r0 = mg * 16 + lg;
            a[0] = SU[Pb + r0 * PSTR + kc + lm];
            a[1] = SU[Pb + (r0 + 8) * PSTR + kc + lm];
            a[2] = SU[Pb + r0 * PSTR + kc + lm + 4];
            a[3] = SU[Pb + (r0 + 8) * PSTR + kc + lm + 4];
            #pragma unroll
            for (int nt = 0; nt < 8; nt++) {
                int nc = ng * 64 + nt * 8 + lg;
                uint32_t b0 = SU[O_V + (kc + lm) * VSTR + nc];
                uint32_t b1 = SU[O_V + (kc + lm + 4) * VSTR + nc];
                mma8(acc2[nt], a, b0, b1);
            }
        }
        __syncthreads();           // V(i) consumed; FAC(i+1) visible
        if (i < NCH - 1) {         // V(i+1) into single buffer
            const float* vc = vb + (size_t)(i + 1) * TKK * HD;
            #pragma unroll
            for (int p = 0; p < 8; p++) {
                int idx = p * 1024 + tid * 4;
                int r = idx >> 7, c = idx & 127;
                CP16(smb + (uint32_t)(O_V + r * VSTR + c) * 4u, vc + idx);
            }
            CP_COMMIT;
        }
    }

    // out epilogue
    #pragma unroll
    for (int hh = 0; hh < 2; hh++) {
        int r = mg * 16 + hh * 8 + lg;
        #pragma unroll
        for (int nt = 0; nt < 8; nt++) {
            int col = ng * 64 + nt * 8 + 2 * lm;
            *(float2*)(ob + (size_t)r * HD + col) =
                make_float2(acc2[nt][2 * hh], acc2[nt][2 * hh + 1]);
        }
    }
}

extern "C" void kernel_launch(void* const* d_in, const int* in_sizes, int n_in,
                              void* d_out, int out_size) {
    const float* q    = (const float*)d_in[0];
    const float* k    = (const float*)d_in[1];
    const float* v    = (const float*)d_in[2];
    const int*   mask = (const int*)d_in[3];
    const float* bias = (const float*)d_in[4];

    float* out  = (float*)d_out;
    float* attn = out + (size_t)BB * HH * SEQ * HD;

    float* kT; cudaGetSymbolAddress((void**)&kT, g_kT);
    float* vT; cudaGetSymbolAddress((void**)&vT, g_vT);

    cudaFuncSetAttribute(k_fused, cudaFuncAttributeMaxDynamicSharedMemorySize, SMEMB);

    const int n4 = (BB * HH * SEQ * HD) / 4;
    const int total = 2 * n4 + NMW;
    k_prep<<<(total + 511) / 512, 512>>>((const float4*)k, (const float4*)v, mask,
                                         (float4*)kT, (float4*)vT, n4);

    dim3 grid(SEQ / TQ, BB * HH);
    k_fused<<<grid, 256, SMEMB>>>(q, bias, attn, out);
}

// round 16
// speedup vs baseline: 1.8547x; 1.0481x over previous
#include <cuda_runtime.h>
#include <cstdint>
#include <cstddef>

#define BB 2
#define HH 16
#define SEQ 2048
#define HD 128
#define TQ 128           // q rows per block
#define TKK 64           // k positions per chunk
#define NCH (SEQ / TKK)  // 32
#define SCALE 0.08838834764831845f

#define STR 132   // stride (floats) Q/K tiles
#define PSTR 68   // stride (floats) P tile
#define VSTR 136  // stride (floats) V tile

// fused smem map (floats); phase A and B regions union.
#define O_Q   0                    // A: [128][132]
#define O_K   16896                // A: [64][132] -> 25344
#define O_P0  0                    // B: [128][68]
#define O_P1  8704                 // B: [128][68] -> 17408
#define O_V   17408                // B: [64][136] -> 26112
#define O_MM  26112                // [128] running max
#define O_LL  26240                // [128] running sum
#define O_IL  26368                // [128] 1/sum
#define O_PMX 26496                // [2][128]
#define O_PSM 26752                // [2][128]
#define O_FAC 27008                // [2][128]
#define SMEM_F 27264
#define SMEMB (SMEM_F * 4)         // 109056 B -> 2 CTAs/SM

#define NMW (BB * SEQ * (SEQ / 32))   // mask words: 262144

// tf32-pre-rounded K/V copies + rm scratch + packed mask bits
__device__ float g_kT[(size_t)BB * HH * SEQ * HD];
__device__ float g_vT[(size_t)BB * HH * SEQ * HD];
__device__ float g_rm[(size_t)BB * HH * 16 * NCH * 256];
__device__ uint32_t g_mk[NMW];     // [b][qrow][kcol/32]

__device__ __forceinline__ uint32_t smem_u32(const void* p) {
    uint32_t a;
    asm("{ .reg .u64 t; cvta.to.shared.u64 t, %1; cvt.u32.u64 %0, t; }"
        : "=r"(a) : "l"(p));
    return a;
}
__device__ __forceinline__ float tf32r(float x) {
    uint32_t u; asm("cvt.rna.tf32.f32 %0, %1;" : "=r"(u) : "f"(x));
    return __uint_as_float(u);
}
__device__ __forceinline__ float4 t4(float4 v) {
    return make_float4(tf32r(v.x), tf32r(v.y), tf32r(v.z), tf32r(v.w));
}
// fast exp on fma/alu pipes, |rel err| ~1e-6 for x <= 0
__device__ __forceinline__ float fexp(float x) {
    x = fmaxf(x, -87.0f);
    float y = x * 1.442695041f;
    float t = y + 12582912.0f;
    int   n = __float_as_int(t) - 0x4B400000;
    float f = y - (t - 12582912.0f);
    float p = 1.33335581e-3f;
    p = fmaf(p, f, 9.61812910e-3f);
    p = fmaf(p, f, 5.55041087e-2f);
    p = fmaf(p, f, 2.40226507e-1f);
    p = fmaf(p, f, 6.93147182e-1f);
    p = fmaf(p, f, 1.0f);
    return p * __int_as_float((n + 127) << 23);
}
__device__ __forceinline__ void mma8(float* c, const uint32_t* a, uint32_t b0, uint32_t b1) {
    asm volatile(
        "mma.sync.aligned.m16n8k8.row.col.f32.tf32.tf32.f32 "
        "{%0,%1,%2,%3}, {%4,%5,%6,%7}, {%8,%9}, {%0,%1,%2,%3};"
        : "+f"(c[0]), "+f"(c[1]), "+f"(c[2]), "+f"(c[3])
        : "r"(a[0]), "r"(a[1]), "r"(a[2]), "r"(a[3]), "r"(b0), "r"(b1));
}
#define CP16(dst, src) \
    asm volatile("cp.async.cg.shared.global [%0], [%1], 16;" :: "r"(dst), "l"(src))
#define CP_COMMIT asm volatile("cp.async.commit_group;" ::: "memory")
#define CP_WAIT0 asm volatile("cp.async.wait_group 0;" ::: "memory")

// k_prep: tf32-round K and V; pack mask into bits.
__global__ __launch_bounds__(512) void k_prep(const float4* __restrict__ ksrc,
                                              const float4* __restrict__ vsrc,
                                              const int* __restrict__ msrc,
                                              float4* __restrict__ kdst,
                                              float4* __restrict__ vdst, int n4) {
    int i = blockIdx.x * 512 + threadIdx.x;
    if (i < n4) {
        kdst[i] = t4(ksrc[i]);
    } else if (i < 2 * n4) {
        vdst[i - n4] = t4(vsrc[i - n4]);
    } else if (i < 2 * n4 + NMW) {
        int j = i - 2 * n4;
        const int4* mp = (const int4*)(msrc + (size_t)j * 32);
        uint32_t bits = 0;
        #pragma unroll
        for (int p = 0; p < 8; p++) {
            int4 m4 = mp[p];
            bits |= (uint32_t)(m4.x != 0) << (4 * p);
            bits |= (uint32_t)(m4.y != 0) << (4 * p + 1);
            bits |= (uint32_t)(m4.z != 0) << (4 * p + 2);
            bits |= (uint32_t)(m4.w != 0) << (4 * p + 3);
        }
        g_mk[j] = bits;
    }
}

// ---------------------------------------------------------------------------
// Fused attention, TQ=128, 2 CTAs/SM. grid (16 qt, 32 bh), 256 thr (8 warps).
// Phase A: warp tile 32x32 (4M x 2N). Phase B: warp tile 32x64 (4M x 2N).
// ---------------------------------------------------------------------------
__global__ __launch_bounds__(256, 2) void k_fused(
    const float* __restrict__ q,
    const float* __restrict__ bias, float* __restrict__ attn,
    float* __restrict__ out) {
    extern __shared__ float S[];
    uint32_t* SU = (uint32_t*)S;
    const uint32_t smb = smem_u32(S);
    const int tid = threadIdx.x, w = tid >> 5, lane = tid & 31;
    const int qt = blockIdx.x, bh = blockIdx.y, b = bh >> 4, h = bh & 15;
    const int mg = w >> 1, ng = w & 1;
    const int lg = lane >> 2, lm = lane & 3;

    const float* qb = q + ((size_t)bh * SEQ + (size_t)qt * TQ) * HD;
    const float* kb = g_kT + (size_t)bh * SEQ * HD;
    const float* vb = g_vT + (size_t)bh * SEQ * HD;
    float* ab = attn + ((size_t)bh * SEQ + (size_t)qt * TQ) * SEQ;
    const float* bb = bias + ((size_t)h * SEQ + (size_t)qt * TQ) * SEQ;
    const uint32_t* mkb = g_mk + ((size_t)b * SEQ + (size_t)qt * TQ) * (SEQ / 32);
    float* ob = out + ((size_t)bh * SEQ + (size_t)qt * TQ) * HD;
    const size_t grmb = (size_t)(bh * 16 + qt) * (NCH * 256);

    // ---------------- phase A: e-scores + online (m, l) ----------------
    #pragma unroll
    for (int p = 0; p < 16; p++) {   // Q: 128 x 128
        int idx = p * 1024 + tid * 4;
        int r = idx >> 7, c = idx & 127;
        float4 qv = *(const float4*)(qb + idx);
        qv.x *= SCALE; qv.y *= SCALE; qv.z *= SCALE; qv.w *= SCALE;
        *(float4*)(S + O_Q + r * STR + c) = t4(qv);
    }
    if (tid < 128) { S[O_MM + tid] = -3.0e38f; S[O_LL + tid] = 0.0f; }
    #pragma unroll
    for (int p = 0; p < 8; p++) {    // K(0): 64 x 128
        int idx = p * 1024 + tid * 4;
        int r = idx >> 7, c = idx & 127;
        CP16(smb + (uint32_t)(O_K + r * STR + c) * 4u, kb + idx);
    }
    CP_COMMIT;

    for (int i = 0; i < NCH; i++) {
        CP_WAIT0;
        __syncthreads();           // K(i) + partials(i-1) visible
        if (tid < 128 && i > 0) {  // merge chunk i-1 stats
            float m0 = S[O_PMX + tid], m1 = S[O_PMX + 128 + tid];
            float mn = fmaxf(S[O_MM + tid], fmaxf(m0, m1));
            S[O_LL + tid] = S[O_LL + tid] * fexp(S[O_MM + tid] - mn) +
                            S[O_PSM + tid] * fexp(m0 - mn) +
                            S[O_PSM + 128 + tid] * fexp(m1 - mn);
            S[O_MM + tid] = mn;
        }

        float acc[2][4][4];
        #pragma unroll
        for (int mt = 0; mt < 2; mt++)
            #pragma unroll
            for (int nt = 0; nt < 4; nt++)
                #pragma unroll
                for (int j = 0; j < 4; j++) acc[mt][nt][j] = 0.0f;

        #pragma unroll 4
        for (int ks = 0; ks < 16; ks++) {
            const int kc = ks * 8;
            uint32_t a[2][4];
            #pragma unroll
            for (int mt = 0; mt < 2; mt++) {
                int r0 = mg * 32 + mt * 16 + lg;
                a[mt][0] = SU[O_Q + r0 * STR + kc + lm];
                a[mt][1] = SU[O_Q + (r0 + 8) * STR + kc + lm];
                a[mt][2] = SU[O_Q + r0 * STR + kc + lm + 4];
                a[mt][3] = SU[O_Q + (r0 + 8) * STR + kc + lm + 4];
            }
            #pragma unroll
            for (int nt = 0; nt < 4; nt++) {
                int nr = ng * 32 + nt * 8 + lg;
                uint32_t b0 = SU[O_K + nr * STR + kc + lm];
                uint32_t b1 = SU[O_K + nr * STR + kc + lm + 4];
                mma8(acc[0][nt], a[0], b0, b1);
                mma8(acc[1][nt], a[1], b0, b1);
            }
        }
        __syncthreads();           // K(i) consumed
        if (i < NCH - 1) {         // K(i+1) load overlaps long epilogue
            const float* kc2 = kb + (size_t)(i + 1) * TKK * HD;
            #pragma unroll
            for (int p = 0; p < 8; p++) {
                int idx = p * 1024 + tid * 4;
                int r = idx >> 7, c = idx & 127;
                CP16(smb + (uint32_t)(O_K + r * STR + c) * 4u, kc2 + idx);
            }
            CP_COMMIT;
        }

        // epilogue: bias + mask bits, rm, store e=exp(s-rm), warp-local sums
        #pragma unroll
        for (int mt = 0; mt < 2; mt++)
        #pragma unroll
        for (int hh = 0; hh < 2; hh++) {
            int r = mg * 32 + mt * 16 + hh * 8 + lg;
            const size_t rb = (size_t)r * SEQ + (size_t)i * TKK + ng * 32 + 2 * lm;
            const uint32_t mw = mkb[(size_t)r * (SEQ / 32) + i * 2 + ng];
            float rm = -3.0e38f;
            float sv[8];
            #pragma unroll
            for (int nt = 0; nt < 4; nt++) {
                float2 bv = *(const float2*)(bb + rb + nt * 8);
                float s0 = acc[mt][nt][2 * hh] + bv.x;
                float s1 = acc[mt][nt][2 * hh + 1] + bv.y;
                if (!((mw >> (nt * 8 + 2 * lm)) & 1u)) s0 = -1.0e9f;
                if (!((mw >> (nt * 8 + 2 * lm + 1)) & 1u)) s1 = -1.0e9f;
                sv[2 * nt] = s0; sv[2 * nt + 1] = s1;
                rm = fmaxf(rm, fmaxf(s0, s1));
            }
            rm = fmaxf(rm, __shfl_xor_sync(0xffffffffu, rm, 1));
            rm = fmaxf(rm, __shfl_xor_sync(0xffffffffu, rm, 2));
            float e = 0.0f;
            #pragma unroll
            for (int j = 0; j < 8; j++) { sv[j] = fexp(sv[j] - rm); e += sv[j]; }
            #pragma unroll
            for (int nt = 0; nt < 4; nt++)
                *(float2*)(ab + rb + nt * 8) = make_float2(sv[2 * nt], sv[2 * nt + 1]);
            e += __shfl_xor_sync(0xffffffffu, e, 1);
            e += __shfl_xor_sync(0xffffffffu, e, 2);
            if (lm == 0) {
                S[O_PMX + ng * 128 + r] = rm;
                S[O_PSM + ng * 128 + r] = e;
                g_rm[grmb + (size_t)i * 256 + ng * 128 + r] = rm;
            }
        }
    }
    __syncthreads();               // last partials visible; phase A smem dead
    if (tid < 128) {               // final merge + inverse
        float m0 = S[O_PMX + tid], m1 = S[O_PMX + 128 + tid];
        float mn = fmaxf(S[O_MM + tid], fmaxf(m0, m1));
        float ll = S[O_LL + tid] * fexp(S[O_MM + tid] - mn) +
                   S[O_PSM + tid] * fexp(m0 - mn) +
                   S[O_PSM + 128 + tid] * fexp(m1 - mn);
        S[O_MM + tid] = mn;
        S[O_IL + tid] = 1.0f / ll;
    }

    // ---------------- phase B: attn = e*fac + P @ V ----------------
    #pragma unroll
    for (int p = 0; p < 8; p++) {   // P(0): 128 x 64
        int idx = p * 1024 + tid * 4;
        int r = idx >> 6, c = idx & 63;
        CP16(smb + (uint32_t)(O_P0 + r * PSTR + c) * 4u,
             ab + (size_t)r * SEQ + c);
    }
    #pragma unroll
    for (int p = 0; p < 8; p++) {   // V(0): 64 x 128
        int idx = p * 1024 + tid * 4;
        int r = idx >> 7, c = idx & 127;
        CP16(smb + (uint32_t)(O_V + r * VSTR + c) * 4u, vb + idx);
    }
    CP_COMMIT;
    __syncthreads();               // MM/IL visible

    // factors for chunk 0 + prefetch rm(1); tid covers all 256 entries
    float rmreg;
    {
        int rr = tid & 127;
        float rm0 = g_rm[grmb + tid];
        S[O_FAC + tid] = fexp(rm0 - S[O_MM + rr]) * S[O_IL + rr];
        rmreg = g_rm[grmb + 256 + tid];
    }

    float acc2[2][8][4];           // warp tile 32 x 64
    #pragma unroll
    for (int mt = 0; mt < 2; mt++)
        #pragma unroll
        for (int nt = 0; nt < 8; nt++)
            #pragma unroll
            for (int j = 0; j < 4; j++) acc2[mt][nt][j] = 0.0f;
    __syncthreads();               // FAC(0) visible

    for (int i = 0; i < NCH; i++) {
        const int Pb = (i & 1) ? O_P1 : O_P0;
        CP_WAIT0;                  // P(i) + V(i) landed
        #pragma unroll
        for (int p = 0; p < 8; p++) {
            int idx = p * 1024 + tid * 4;
            int r = idx >> 6, c = idx & 63;
            float4 e4 = *(float4*)(S + Pb + r * PSTR + c);
            float f = S[O_FAC + ((c >> 5) << 7) + r];
            float4 p4 = make_float4(e4.x * f, e4.y * f, e4.z * f, e4.w * f);
            *(float4*)(ab + (size_t)r * SEQ + (size_t)i * TKK + c) = p4;
            *(float4*)(S + Pb + r * PSTR + c) = t4(p4);
        }
        __syncthreads();           // staging done; FAC(i) consumed
        if (i < NCH - 1) {         // P(i+1) load + FAC(i+1) overlap MMA(i)
            const int Pn = (i & 1) ? O_P0 : O_P1;
            #pragma unroll
            for (int p = 0; p < 8; p++) {
                int idx = p * 1024 + tid * 4;
                int r = idx >> 6, c = idx & 63;
                CP16(smb + (uint32_t)(Pn + r * PSTR + c) * 4u,
                     ab + (size_t)r * SEQ + (size_t)(i + 1) * TKK + c);
            }
            CP_COMMIT;
            {
                int rr = tid & 127;
                S[O_FAC + tid] = fexp(rmreg - S[O_MM + rr]) * S[O_IL + rr];
                if (i < NCH - 2) rmreg = g_rm[grmb + (size_t)(i + 2) * 256 + tid];
            }
        }

        #pragma unroll 2
        for (int ks = 0; ks < 8; ks++) {
            const int kc = ks * 8;
            uint32_t a[2][4];
            #pragma unroll
            for (int mt = 0; mt < 2; mt++) {
                int r0 = mg * 32 + mt * 16 + lg;
                a[mt][0] = SU[Pb + r0 * PSTR + kc + lm];
                a[mt][1] = SU[Pb + (r0 + 8) * PSTR + kc + lm];
                a[mt][2] = SU[Pb + r0 * PSTR + kc + lm + 4];
                a[mt][3] = SU[Pb + (r0 + 8) * PSTR + kc + lm + 4];
            }
            #pragma unroll
            for (int nt = 0; nt < 8; nt++) {
                int nc = ng * 64 + nt * 8 + lg;
                uint32_t b0 = SU[O_V + (kc + lm) * VSTR + nc];
                uint32_t b1 = SU[O_V + (kc + lm + 4) * VSTR + nc];
                mma8(acc2[0][nt], a[0], b0, b1);
                mma8(acc2[1][nt], a[1], b0, b1);
            }
        }
        __syncthreads();           // V(i) consumed; FAC(i+1) visible
        if (i < NCH - 1) {         // V(i+1) into single buffer
            const float* vc = vb + (size_t)(i + 1) * TKK * HD;
            #pragma unroll
            for (int p = 0; p < 8; p++) {
                int idx = p * 1024 + tid * 4;
                int r = idx >> 7, c = idx & 127;
                CP16(smb + (uint32_t)(O_V + r * VSTR + c) * 4u, vc + idx);
            }
            CP_COMMIT;
        }
    }

    // out epilogue
    #pragma unroll
    for (int mt = 0; mt < 2; mt++)
    #pragma unroll
    for (int hh = 0; hh < 2; hh++) {
        int r = mg * 32 + mt * 16 + hh * 8 + lg;
        #pragma unroll
        for (int nt = 0; nt < 8; nt++) {
            int col = ng * 64 + nt * 8 + 2 * lm;
            *(float2*)(ob + (size_t)r * HD + col) =
                make_float2(acc2[mt][nt][2 * hh], acc2[mt][nt][2 * hh + 1]);
        }
    }
}

extern "C" void kernel_launch(void* const* d_in, const int* in_sizes, int n_in,
                              void* d_out, int out_size) {
    const float* q    = (const float*)d_in[0];
    const float* k    = (const float*)d_in[1];
    const float* v    = (const float*)d_in[2];
    const int*   mask = (const int*)d_in[3];
    const float* bias = (const float*)d_in[4];

    float* out  = (float*)d_out;
    float* attn = out + (size_t)BB * HH * SEQ * HD;

    float* kT; cudaGetSymbolAddress((void**)&kT, g_kT);
    float* vT; cudaGetSymbolAddress((void**)&vT, g_vT);

    cudaFuncSetAttribute(k_fused, cudaFuncAttributeMaxDynamicSharedMemorySize, SMEMB);

    const int n4 = (BB * HH * SEQ * HD) / 4;
    const int total = 2 * n4 + NMW;
    k_prep<<<(total + 511) / 512, 512>>>((const float4*)k, (const float4*)v, mask,
                                         (float4*)kT, (float4*)vT, n4);

    dim3 grid(SEQ / TQ, BB * HH);
    k_fused<<<grid, 256, SMEMB>>>(q, bias, attn, out);
}